// round 2
// baseline (speedup 1.0000x reference)
#include <cuda_runtime.h>
#include <math.h>
#include <float.h>
#include <limits.h>

// Problem constants
#define NTOK 4096      // B*S
#define DDIM 768
#define LDIM 256
#define VOC  50265
#define KSEL 4
#define NSPLIT 8
#define SPLIT_SZ 6284  // ceil(VOC/NSPLIT)

typedef unsigned long long u64t;

// ---------------- scratch (device globals; no allocations) ----------------
__device__ float  g_zi_pre[NTOK * LDIM];      // x@W_in+b (kept for mse2 ref)
__device__ float  g_zi[NTOK * LDIM];          // normalized
__device__ float  g_zc[VOC * LDIM];           // codebook@W_code+b, normalized in place
__device__ float  g_q[NTOK * DDIM];           // quantized
__device__ float  g_pt_val[NTOK * NSPLIT * KSEL];
__device__ int    g_pt_idx[NTOK * NSPLIT * KSEL];
__device__ int    g_idx[NTOK * KSEL];
__device__ int    g_counts[VOC];
__device__ double g_mse1, g_mse2, g_ent;
__device__ int    g_nz;

// ---------------- f32x2 packed helpers ----------------
__device__ __forceinline__ u64t pack2(float lo, float hi) {
    u64t r; asm("mov.b64 %0,{%1,%2};" : "=l"(r) : "f"(lo), "f"(hi)); return r;
}
__device__ __forceinline__ u64t dup2(float v) {
    u64t r; asm("mov.b64 %0,{%1,%1};" : "=l"(r) : "f"(v)); return r;
}
__device__ __forceinline__ void fma2(u64t& d, u64t a, u64t b) {
    asm("fma.rn.f32x2 %0,%1,%2,%0;" : "+l"(d) : "l"(a), "l"(b));
}
__device__ __forceinline__ float2 unpack2(u64t v) {
    float2 f; asm("mov.b64 {%0,%1},%2;" : "=f"(f.x), "=f"(f.y) : "l"(v)); return f;
}

// ---------------- topk helpers ----------------
__device__ __forceinline__ bool better(float v, int j, float v2, int j2) {
    return (v > v2) || (v == v2 && j < j2);
}
__device__ __forceinline__ void ins4(float v, int j, float tv[4], int ti[4]) {
    if (!better(v, j, tv[3], ti[3])) return;
    tv[3] = v; ti[3] = j;
#pragma unroll
    for (int k = 3; k > 0; k--) {
        if (better(tv[k], ti[k], tv[k-1], ti[k-1])) {
            float fv = tv[k]; tv[k] = tv[k-1]; tv[k-1] = fv;
            int   fi = ti[k]; ti[k] = ti[k-1]; ti[k-1] = fi;
        }
    }
}

// ---------------- init ----------------
__global__ void init_k() {
    int i = blockIdx.x * blockDim.x + threadIdx.x;
    for (int v = i; v < VOC; v += gridDim.x * blockDim.x) g_counts[v] = 0;
    if (i == 0) { g_mse1 = 0.0; g_mse2 = 0.0; g_ent = 0.0; g_nz = 0; }
}

// ---------------- GEMM: C[M,256] = A[M,768] @ W[768,256] + bias -----------
// 64x128 tile, 256 threads, each 4 rows x 8 cols via f32x2 packed FMA.
// MODE 0: write C.  MODE 1: accumulate sum((C - ref)^2) into g_mse2.
template <int MODE>
__global__ void __launch_bounds__(256, 2)
gemm_k(const float* __restrict__ A, const float* __restrict__ W,
       const float* __restrict__ bias, float* __restrict__ C,
       const float* __restrict__ ref, int M)
{
    __shared__ float As[32][68];    // k-major: As[k][m]
    __shared__ float Ws[32][136];   // Ws[k][n]
    const int tid = threadIdx.x;
    const int m0 = blockIdx.x * 64, n0 = blockIdx.y * 128;
    const int tx = tid & 15, ty = tid >> 4;

    u64t acc[4][4] = {};
    for (int c0 = 0; c0 < DDIM; c0 += 32) {
#pragma unroll
        for (int t = 0; t < 2; t++) {            // A tile -> transposed store
            int li = tid * 2 + t;
            int row = li >> 3, kq = li & 7;
            float4 v = make_float4(0.f, 0.f, 0.f, 0.f);
            if (m0 + row < M)
                v = *(const float4*)&A[(size_t)(m0 + row) * DDIM + c0 + kq * 4];
            As[kq*4+0][row] = v.x; As[kq*4+1][row] = v.y;
            As[kq*4+2][row] = v.z; As[kq*4+3][row] = v.w;
        }
#pragma unroll
        for (int t = 0; t < 4; t++) {            // W tile -> direct store
            int li = tid * 4 + t;
            int r = li >> 5, nq = li & 31;
            float4 v = *(const float4*)&W[(size_t)(c0 + r) * LDIM + n0 + nq * 4];
            *(float4*)&Ws[r][nq * 4] = v;
        }
        __syncthreads();
#pragma unroll
        for (int kk = 0; kk < 32; kk++) {
            float4 a4 = *(float4*)&As[kk][ty * 4];
            float4 b0 = *(float4*)&Ws[kk][tx * 8];
            float4 b1 = *(float4*)&Ws[kk][tx * 8 + 4];
            u64t bb[4] = {pack2(b0.x, b0.y), pack2(b0.z, b0.w),
                          pack2(b1.x, b1.y), pack2(b1.z, b1.w)};
            u64t aa[4] = {dup2(a4.x), dup2(a4.y), dup2(a4.z), dup2(a4.w)};
#pragma unroll
            for (int i = 0; i < 4; i++)
#pragma unroll
                for (int j = 0; j < 4; j++)
                    fma2(acc[i][j], aa[i], bb[j]);
        }
        __syncthreads();
    }

    if (MODE == 0) {
#pragma unroll
        for (int i = 0; i < 4; i++) {
            int row = m0 + ty * 4 + i;
            if (row < M) {
#pragma unroll
                for (int j = 0; j < 4; j++) {
                    int col = n0 + tx * 8 + j * 2;
                    float2 f = unpack2(acc[i][j]);
                    C[(size_t)row * LDIM + col]     = f.x + bias[col];
                    C[(size_t)row * LDIM + col + 1] = f.y + bias[col + 1];
                }
            }
        }
    } else {
        double s = 0.0;
#pragma unroll
        for (int i = 0; i < 4; i++) {
            int row = m0 + ty * 4 + i;
            if (row < M) {
#pragma unroll
                for (int j = 0; j < 4; j++) {
                    int col = n0 + tx * 8 + j * 2;
                    float2 f = unpack2(acc[i][j]);
                    float d0 = f.x + bias[col]     - ref[(size_t)row * LDIM + col];
                    float d1 = f.y + bias[col + 1] - ref[(size_t)row * LDIM + col + 1];
                    s += (double)d0 * (double)d0 + (double)d1 * (double)d1;
                }
            }
        }
#pragma unroll
        for (int off = 16; off > 0; off >>= 1)
            s += __shfl_down_sync(0xFFFFFFFFu, s, off);
        if ((tid & 31) == 0) atomicAdd(&g_mse2, s);
    }
}

// ---------------- row L2-normalize ----------------------------------------
__global__ void norm_k(const float* __restrict__ in, float* __restrict__ out, int M)
{
    int w = (blockIdx.x * blockDim.x + threadIdx.x) >> 5;
    int lane = threadIdx.x & 31;
    if (w >= M) return;
    const float* r = in + (size_t)w * LDIM;
    float vals[8];
    float s = 0.f;
#pragma unroll
    for (int i = 0; i < 8; i++) { vals[i] = r[lane + 32 * i]; s += vals[i] * vals[i]; }
#pragma unroll
    for (int off = 16; off > 0; off >>= 1)
        s += __shfl_xor_sync(0xFFFFFFFFu, s, off);
    float t = s + 1e-12f;
    float sc = rsqrtf(t);
    sc = sc * (1.5f - 0.5f * t * sc * sc);   // Newton: ~1 ulp
    float* o = out + (size_t)w * LDIM;
#pragma unroll
    for (int i = 0; i < 8; i++) o[lane + 32 * i] = vals[i] * sc;
}

// ---------------- fused distance + per-split top-4 ------------------------
// grid: (NTOK/64, NSPLIT). 64 tokens x 128 codes per tile, f32x2 FMA.
__global__ void __launch_bounds__(256, 2)
topk_k(const float* __restrict__ zi, const float* __restrict__ zc,
       float* __restrict__ pval, int* __restrict__ pidx)
{
    // union: {As[32][68] + Bs[32][136]} overlapped with scs[64][132]
    __shared__ __align__(16) char smembuf[64 * 132 * 4];
    float (*As)[68]   = (float(*)[68])smembuf;
    float (*Bs)[136]  = (float(*)[136])(smembuf + 32 * 68 * 4);
    float (*scs)[132] = (float(*)[132])smembuf;

    const int tid = threadIdx.x;
    const int t0 = blockIdx.x * 64;
    const int split = blockIdx.y;
    const int j0 = split * SPLIT_SZ;
    const int jend = min(VOC, j0 + SPLIT_SZ);
    const int tx = tid & 15, ty = tid >> 4;
    const int tok = tid >> 2, qq = tid & 3;

    float tv[4] = {-FLT_MAX, -FLT_MAX, -FLT_MAX, -FLT_MAX};
    int   ti[4] = {INT_MAX, INT_MAX, INT_MAX, INT_MAX};

    for (int jc = j0; jc < jend; jc += 128) {
        u64t acc[4][4] = {};
        for (int c0 = 0; c0 < LDIM; c0 += 32) {
#pragma unroll
            for (int t = 0; t < 2; t++) {        // zi tile (64 x 32)
                int li = tid * 2 + t;
                int row = li >> 3, kq = li & 7;
                float4 v = *(const float4*)&zi[(size_t)(t0 + row) * LDIM + c0 + kq * 4];
                As[kq*4+0][row] = v.x; As[kq*4+1][row] = v.y;
                As[kq*4+2][row] = v.z; As[kq*4+3][row] = v.w;
            }
#pragma unroll
            for (int t = 0; t < 4; t++) {        // zc tile (128 x 32)
                int li = tid * 4 + t;
                int row = li >> 3, kq = li & 7;
                int j = jc + row;
                float4 v = make_float4(0.f, 0.f, 0.f, 0.f);
                if (j < VOC)
                    v = *(const float4*)&zc[(size_t)j * LDIM + c0 + kq * 4];
                Bs[kq*4+0][row] = v.x; Bs[kq*4+1][row] = v.y;
                Bs[kq*4+2][row] = v.z; Bs[kq*4+3][row] = v.w;
            }
            __syncthreads();
#pragma unroll
            for (int kk = 0; kk < 32; kk++) {
                float4 a4 = *(float4*)&As[kk][ty * 4];
                float4 b0 = *(float4*)&Bs[kk][tx * 8];
                float4 b1 = *(float4*)&Bs[kk][tx * 8 + 4];
                u64t bb[4] = {pack2(b0.x, b0.y), pack2(b0.z, b0.w),
                              pack2(b1.x, b1.y), pack2(b1.z, b1.w)};
                u64t aa[4] = {dup2(a4.x), dup2(a4.y), dup2(a4.z), dup2(a4.w)};
#pragma unroll
                for (int i = 0; i < 4; i++)
#pragma unroll
                    for (int j = 0; j < 4; j++)
                        fma2(acc[i][j], aa[i], bb[j]);
            }
            __syncthreads();
        }
        // dump scores to smem (As/Bs dead until next jc iteration)
#pragma unroll
        for (int i = 0; i < 4; i++)
#pragma unroll
            for (int j = 0; j < 4; j++) {
                float2 f = unpack2(acc[i][j]);
                scs[ty * 4 + i][tx * 8 + j * 2]     = f.x;
                scs[ty * 4 + i][tx * 8 + j * 2 + 1] = f.y;
            }
        __syncthreads();
        // each token scanned by 4 threads, 32 codes each
#pragma unroll
        for (int s = 0; s < 32; s++) {
            int cl = qq * 32 + s;
            int j = jc + cl;
            if (j < jend) ins4(scs[tok][cl], j, tv, ti);
        }
        __syncthreads();
    }

    // merge the 4 per-thread quarters of each token (reuse scs as scratch)
    float* mv = &scs[0][0];
    int*   mi = ((int*)&scs[0][0]) + 1024;
#pragma unroll
    for (int k = 0; k < 4; k++) {
        mv[tok * 16 + qq * 4 + k] = tv[k];
        mi[tok * 16 + qq * 4 + k] = ti[k];
    }
    __syncthreads();
    if (qq == 0) {
        float bv[4] = {-FLT_MAX, -FLT_MAX, -FLT_MAX, -FLT_MAX};
        int   bi[4] = {INT_MAX, INT_MAX, INT_MAX, INT_MAX};
#pragma unroll
        for (int c = 0; c < 16; c++)
            ins4(mv[tok * 16 + c], mi[tok * 16 + c], bv, bi);
        size_t base = ((size_t)(t0 + tok) * NSPLIT + split) * KSEL;
#pragma unroll
        for (int k = 0; k < 4; k++) { pval[base + k] = bv[k]; pidx[base + k] = bi[k]; }
    }
}

// ---------------- merge splits -> final top-4, histogram -------------------
__global__ void merge_k(const float* __restrict__ pval, const int* __restrict__ pidx)
{
    int t = blockIdx.x * blockDim.x + threadIdx.x;
    if (t >= NTOK) return;
    float bv[4] = {-FLT_MAX, -FLT_MAX, -FLT_MAX, -FLT_MAX};
    int   bi[4] = {INT_MAX, INT_MAX, INT_MAX, INT_MAX};
#pragma unroll
    for (int c = 0; c < NSPLIT * KSEL; c++)
        ins4(pval[(size_t)t * NSPLIT * KSEL + c], pidx[(size_t)t * NSPLIT * KSEL + c], bv, bi);
#pragma unroll
    for (int k = 0; k < 4; k++) {
        g_idx[t * 4 + k] = bi[k];
        atomicAdd(&g_counts[bi[k]], 1);
    }
}

// ---------------- quantize -------------------------------------------------
__global__ void quant_k(const float* __restrict__ x, const float* __restrict__ cb,
                        float* __restrict__ out)
{
    int w = (blockIdx.x * blockDim.x + threadIdx.x) >> 5;   // token
    int lane = threadIdx.x & 31;
    if (w >= NTOK) return;
    const float* c0 = cb + (size_t)g_idx[w * 4 + 0] * DDIM;
    const float* c1 = cb + (size_t)g_idx[w * 4 + 1] * DDIM;
    const float* c2 = cb + (size_t)g_idx[w * 4 + 2] * DDIM;
    const float* c3 = cb + (size_t)g_idx[w * 4 + 3] * DDIM;
    double s = 0.0;
    for (int c = lane; c < DDIM; c += 32) {
        float qv = (((c0[c] + c1[c]) + c2[c]) + c3[c]) * 0.25f;
        float xv = x[(size_t)w * DDIM + c];
        float d = qv - xv;
        out[(size_t)w * DDIM + c] = xv + d;     // x + (q - x), matches STE
        g_q[(size_t)w * DDIM + c] = qv;
        s += (double)d * (double)d;
    }
#pragma unroll
    for (int off = 16; off > 0; off >>= 1)
        s += __shfl_down_sync(0xFFFFFFFFu, s, off);
    if (lane == 0) atomicAdd(&g_mse1, s);
}

// ---------------- entropy / usage ------------------------------------------
__global__ void ent_k()
{
    int i0 = blockIdx.x * blockDim.x + threadIdx.x;
    double e = 0.0; int nz = 0;
    for (int i = i0; i < VOC; i += gridDim.x * blockDim.x) {
        int c = g_counts[i];
        if (c > 0) {
            float p = (float)c * (1.0f / (NTOK * KSEL));
            e += (double)(p * logf(p + 1e-10f));
            nz++;
        }
    }
#pragma unroll
    for (int off = 16; off > 0; off >>= 1) {
        e  += __shfl_down_sync(0xFFFFFFFFu, e, off);
        nz += __shfl_down_sync(0xFFFFFFFFu, nz, off);
    }
    if ((threadIdx.x & 31) == 0) { atomicAdd(&g_ent, e); atomicAdd(&g_nz, nz); }
}

// ---------------- finalize scalars -----------------------------------------
__global__ void fin_k(float* __restrict__ out3)
{
    float lp = (float)(-g_ent);
    float mse1 = (float)(g_mse1 / ((double)NTOK * DDIM));
    float mse2 = (float)(g_mse2 / ((double)NTOK * LDIM));
    float loss = 1.25f * mse1 + 1.25f * mse2 + 0.1f * lp;
    out3[0] = loss;
    out3[1] = expf(lp);
    out3[2] = (float)g_nz / (float)VOC / (float)KSEL;
}

// ---------------- launch ----------------------------------------------------
static float* sym_f(const void* s) { void* p = nullptr; cudaGetSymbolAddress(&p, s); return (float*)p; }
static int*   sym_i(const void* s) { void* p = nullptr; cudaGetSymbolAddress(&p, s); return (int*)p; }

extern "C" void kernel_launch(void* const* d_in, const int* in_sizes, int n_in,
                              void* d_out, int out_size)
{
    const float* x  = (const float*)d_in[0];
    const float* cb = (const float*)d_in[1];
    const float* Wi = (const float*)d_in[2];
    const float* bi = (const float*)d_in[3];
    const float* Wc = (const float*)d_in[4];
    const float* bc = (const float*)d_in[5];
    float* out = (float*)d_out;

    float* zi_pre = sym_f(g_zi_pre);
    float* zi     = sym_f(g_zi);
    float* zc     = sym_f(g_zc);
    float* q      = sym_f(g_q);
    float* pval   = sym_f(g_pt_val);
    int*   pidx   = sym_i(g_pt_idx);

    init_k<<<64, 256>>>();
    // zi_pre = x @ W_in + b_in ; zi = l2n(zi_pre)
    gemm_k<0><<<dim3(NTOK / 64, LDIM / 128), 256>>>(x, Wi, bi, zi_pre, nullptr, NTOK);
    norm_k<<<NTOK / 8, 256>>>(zi_pre, zi, NTOK);
    // zc = l2n(codebook @ W_code + b_code)
    gemm_k<0><<<dim3((VOC + 63) / 64, LDIM / 128), 256>>>(cb, Wc, bc, zc, nullptr, VOC);
    norm_k<<<(VOC + 7) / 8, 256>>>(zc, zc, VOC);
    // fused distance + top-4
    topk_k<<<dim3(NTOK / 64, NSPLIT), 256>>>(zi, zc, pval, pidx);
    merge_k<<<NTOK / 256, 256>>>(pval, pidx);
    // quantize + STE output + mse1
    quant_k<<<NTOK / 8, 256>>>(x, cb, out);
    // mse2 = sum((q @ W_code + b_code - zi_pre)^2)
    gemm_k<1><<<dim3(NTOK / 64, LDIM / 128), 256>>>(q, Wc, bc, nullptr, zi_pre, NTOK);
    ent_k<<<64, 256>>>();
    fin_k<<<1, 1>>>(out + (size_t)NTOK * DDIM);
}

// round 3
// speedup vs baseline: 1.8147x; 1.8147x over previous
#include <cuda_runtime.h>
#include <cuda_bf16.h>
#include <math.h>
#include <float.h>
#include <limits.h>

// Problem constants
#define NTOK 4096      // B*S
#define DDIM 768
#define LDIM 256
#define VOC  50265
#define KSEL 4
#define NSPLIT 9
#define SPLIT_SZ 5585  // 9*5585 == 50265 exactly
#define NCAND (NSPLIT * 8)   // 72 candidates per token

// ---------------- scratch (device globals; no allocations) ----------------
__device__ float  g_zi_pre[NTOK * LDIM];      // x@W_in+b (kept for mse2 ref)
__device__ float  g_zi[NTOK * LDIM];          // normalized
__device__ float  g_zc[VOC * LDIM];           // codebook@W_code+b, normalized
__device__ float  g_q[NTOK * DDIM];           // quantized
__device__ __nv_bfloat16 g_zih[NTOK * LDIM];
__device__ __nv_bfloat16 g_zim[NTOK * LDIM];
__device__ __nv_bfloat16 g_zch[VOC * LDIM];
__device__ __nv_bfloat16 g_zcm[VOC * LDIM];
__device__ int    g_cand[NTOK * NCAND];
__device__ int    g_idx[NTOK * KSEL];
__device__ int    g_counts[VOC];
__device__ double g_mse1, g_mse2, g_ent;
__device__ int    g_nz;

// ---------------- topk helpers ----------------
__device__ __forceinline__ bool better(float v, int j, float v2, int j2) {
    return (v > v2) || (v == v2 && j < j2);
}
__device__ __forceinline__ void ins4(float v, int j, float tv[4], int ti[4]) {
    if (!better(v, j, tv[3], ti[3])) return;
    tv[3] = v; ti[3] = j;
#pragma unroll
    for (int k = 3; k > 0; k--) {
        if (better(tv[k], ti[k], tv[k-1], ti[k-1])) {
            float fv = tv[k]; tv[k] = tv[k-1]; tv[k-1] = fv;
            int   fi = ti[k]; ti[k] = ti[k-1]; ti[k-1] = fi;
        }
    }
}
__device__ __forceinline__ void ins8(float v, int j, float tv[8], int ti[8]) {
    if (!better(v, j, tv[7], ti[7])) return;
    tv[7] = v; ti[7] = j;
#pragma unroll
    for (int k = 7; k > 0; k--) {
        if (better(tv[k], ti[k], tv[k-1], ti[k-1])) {
            float fv = tv[k]; tv[k] = tv[k-1]; tv[k-1] = fv;
            int   fi = ti[k]; ti[k] = ti[k-1]; ti[k-1] = fi;
        }
    }
}

// ---------------- bf16 mma helper ----------------
__device__ __forceinline__ void mma_bf16(float d[4], const unsigned a[4], const unsigned b[2]) {
    asm("mma.sync.aligned.m16n8k16.row.col.f32.bf16.bf16.f32 "
        "{%0,%1,%2,%3},{%4,%5,%6,%7},{%8,%9},{%0,%1,%2,%3};"
        : "+f"(d[0]), "+f"(d[1]), "+f"(d[2]), "+f"(d[3])
        : "r"(a[0]), "r"(a[1]), "r"(a[2]), "r"(a[3]), "r"(b[0]), "r"(b[1]));
}

// ---------------- init ----------------
__global__ void init_k() {
    int i = blockIdx.x * blockDim.x + threadIdx.x;
    for (int v = i; v < VOC; v += gridDim.x * blockDim.x) g_counts[v] = 0;
    if (i == 0) { g_mse1 = 0.0; g_mse2 = 0.0; g_ent = 0.0; g_nz = 0; }
}

// ---------------- GEMM (R1 proven): C[M,256] = A[M,768] @ W + bias --------
template <int MODE>
__global__ void __launch_bounds__(256, 2)
gemm_k(const float* __restrict__ A, const float* __restrict__ W,
       const float* __restrict__ bias, float* __restrict__ C,
       const float* __restrict__ ref, int M)
{
    __shared__ float As[32][68];   // k-major: As[k][m]
    __shared__ float Ws[32][68];   // Ws[k][n]
    const int tid = threadIdx.x;
    const int m0 = blockIdx.x * 64, n0 = blockIdx.y * 64;
    const int tx = tid & 15, ty = tid >> 4;

    float acc[4][4] = {};
    for (int c0 = 0; c0 < DDIM; c0 += 32) {
#pragma unroll
        for (int t = 0; t < 2; t++) {            // A tile -> transposed store
            int li = tid * 2 + t;
            int row = li >> 3, kq = li & 7;
            float4 v = make_float4(0.f, 0.f, 0.f, 0.f);
            if (m0 + row < M)
                v = *(const float4*)&A[(size_t)(m0 + row) * DDIM + c0 + kq * 4];
            As[kq*4+0][row] = v.x; As[kq*4+1][row] = v.y;
            As[kq*4+2][row] = v.z; As[kq*4+3][row] = v.w;
        }
#pragma unroll
        for (int t = 0; t < 2; t++) {            // W tile -> direct store
            int li = tid * 2 + t;
            int r = li >> 4, nq = li & 15;
            float4 v = *(const float4*)&W[(size_t)(c0 + r) * LDIM + n0 + nq * 4];
            *(float4*)&Ws[r][nq * 4] = v;
        }
        __syncthreads();
#pragma unroll
        for (int kk = 0; kk < 32; kk++) {
            float4 a4 = *(float4*)&As[kk][ty * 4];
            float4 b4 = *(float4*)&Ws[kk][tx * 4];
            float av[4] = {a4.x, a4.y, a4.z, a4.w};
            float bv[4] = {b4.x, b4.y, b4.z, b4.w};
#pragma unroll
            for (int i = 0; i < 4; i++)
#pragma unroll
                for (int j = 0; j < 4; j++)
                    acc[i][j] += av[i] * bv[j];
        }
        __syncthreads();
    }

    if (MODE == 0) {
#pragma unroll
        for (int i = 0; i < 4; i++) {
            int row = m0 + ty * 4 + i;
            if (row < M) {
#pragma unroll
                for (int j = 0; j < 4; j++) {
                    int col = n0 + tx * 4 + j;
                    C[(size_t)row * LDIM + col] = acc[i][j] + bias[col];
                }
            }
        }
    } else {
        double s = 0.0;
#pragma unroll
        for (int i = 0; i < 4; i++) {
            int row = m0 + ty * 4 + i;
            if (row < M) {
#pragma unroll
                for (int j = 0; j < 4; j++) {
                    int col = n0 + tx * 4 + j;
                    float cv = acc[i][j] + bias[col];
                    float d  = cv - ref[(size_t)row * LDIM + col];
                    s += (double)d * (double)d;
                }
            }
        }
#pragma unroll
        for (int off = 16; off > 0; off >>= 1)
            s += __shfl_down_sync(0xFFFFFFFFu, s, off);
        if ((tid & 31) == 0) atomicAdd(&g_mse2, s);
    }
}

// ---------------- row L2-normalize ----------------------------------------
__global__ void norm_k(const float* __restrict__ in, float* __restrict__ out, int M)
{
    int w = (blockIdx.x * blockDim.x + threadIdx.x) >> 5;
    int lane = threadIdx.x & 31;
    if (w >= M) return;
    const float* r = in + (size_t)w * LDIM;
    float vals[8];
    float s = 0.f;
#pragma unroll
    for (int i = 0; i < 8; i++) { vals[i] = r[lane + 32 * i]; s += vals[i] * vals[i]; }
#pragma unroll
    for (int off = 16; off > 0; off >>= 1)
        s += __shfl_xor_sync(0xFFFFFFFFu, s, off);
    float t = s + 1e-12f;
    float sc = rsqrtf(t);
    sc = sc * (1.5f - 0.5f * t * sc * sc);   // Newton: ~1 ulp
    float* o = out + (size_t)w * LDIM;
#pragma unroll
    for (int i = 0; i < 8; i++) o[lane + 32 * i] = vals[i] * sc;
}

// ---------------- bf16 2-term split ---------------------------------------
__global__ void split_k(const float* __restrict__ in,
                        __nv_bfloat16* __restrict__ oh,
                        __nv_bfloat16* __restrict__ om, int n)
{
    int i = blockIdx.x * blockDim.x + threadIdx.x;
    int stride = gridDim.x * blockDim.x;
    for (; i < n; i += stride) {
        float a = in[i];
        __nv_bfloat16 h = __float2bfloat16(a);
        float hf = __bfloat162float(h);
        oh[i] = h;
        om[i] = __float2bfloat16(a - hf);
    }
}

// ---------------- tensor-core approx scores + top-8 candidates ------------
// grid (NTOK/128, NSPLIT). Tile 128 tokens x 128 codes.
// 8 warps in 4x2 grid; warp computes 32x64 via m16n8k16 bf16 mma.
// score ~= ah.bh + ah.bm + am.bh  (error ~2e-6; exact rescore downstream)
__global__ void __launch_bounds__(256, 1)
topk_mma(const __nv_bfloat16* __restrict__ zih, const __nv_bfloat16* __restrict__ zim,
         const __nv_bfloat16* __restrict__ zch, const __nv_bfloat16* __restrict__ zcm,
         int* __restrict__ cand)
{
    // stage buffers (40960 B) unioned with score tile scs[128][68] (34816 B)
    __shared__ __align__(16) char smembuf[40960];
    char* sAh = smembuf;                 // [128 rows][80 B] (32 bf16 + 8 pad)
    char* sAm = smembuf + 10240;
    char* sBh = smembuf + 20480;
    char* sBm = smembuf + 30720;
    float (*scs)[68] = (float(*)[68])smembuf;

    const int tid = threadIdx.x;
    const int w = tid >> 5, lane = tid & 31;
    const int grp = lane >> 2, tig = lane & 3;
    const int wm = w >> 1, wn = w & 1;           // 4 x 2 warp grid
    const int t0 = blockIdx.x * 128;
    const int split = blockIdx.y;
    const int j0 = split * SPLIT_SZ;
    const int jend = j0 + SPLIT_SZ;

    const int lrow = tid >> 1;           // loader: row 0..127
    const int lhk  = (tid & 1) * 16;     // loader: k offset within 32-k stage

    float tv8[8]; int ti8[8];
#pragma unroll
    for (int k = 0; k < 8; k++) { tv8[k] = -FLT_MAX; ti8[k] = INT_MAX; }

    for (int jc = j0; jc < jend; jc += 128) {
        float acc[2][8][4] = {};

        // ---- prologue: stage 0 ----
        {
            const uint4* pa = (const uint4*)(zih + (size_t)(t0 + lrow) * LDIM + lhk);
            const uint4* pm = (const uint4*)(zim + (size_t)(t0 + lrow) * LDIM + lhk);
            uint4 v0 = pa[0], v1 = pa[1], v2 = pm[0], v3 = pm[1];
            uint4 b0 = {0,0,0,0}, b1 = b0, b2 = b0, b3 = b0;
            int j = jc + lrow;
            if (j < jend) {
                const uint4* pb = (const uint4*)(zch + (size_t)j * LDIM + lhk);
                const uint4* pc = (const uint4*)(zcm + (size_t)j * LDIM + lhk);
                b0 = pb[0]; b1 = pb[1]; b2 = pc[0]; b3 = pc[1];
            }
            char* da = sAh + lrow * 80 + lhk * 2;
            char* dm = sAm + lrow * 80 + lhk * 2;
            char* db = sBh + lrow * 80 + lhk * 2;
            char* dc = sBm + lrow * 80 + lhk * 2;
            *(uint4*)da = v0; *(uint4*)(da + 16) = v1;
            *(uint4*)dm = v2; *(uint4*)(dm + 16) = v3;
            *(uint4*)db = b0; *(uint4*)(db + 16) = b1;
            *(uint4*)dc = b2; *(uint4*)(dc + 16) = b3;
        }
        __syncthreads();

        for (int s = 0; s < 8; s++) {          // 8 stages of 32 k-dims
            uint4 n0v, n1v, n2v, n3v, n4v, n5v, n6v, n7v;
            bool pf = (s < 7);
            if (pf) {                          // prefetch next stage into regs
                int ko = (s + 1) * 32 + lhk;
                const uint4* pa = (const uint4*)(zih + (size_t)(t0 + lrow) * LDIM + ko);
                const uint4* pm = (const uint4*)(zim + (size_t)(t0 + lrow) * LDIM + ko);
                n0v = pa[0]; n1v = pa[1]; n2v = pm[0]; n3v = pm[1];
                uint4 z = {0,0,0,0};
                n4v = z; n5v = z; n6v = z; n7v = z;
                int j = jc + lrow;
                if (j < jend) {
                    const uint4* pb = (const uint4*)(zch + (size_t)j * LDIM + ko);
                    const uint4* pc = (const uint4*)(zcm + (size_t)j * LDIM + ko);
                    n4v = pb[0]; n5v = pb[1]; n6v = pc[0]; n7v = pc[1];
                }
            }
            // ---- mma on current stage ----
#pragma unroll
            for (int ks = 0; ks < 2; ks++) {
                unsigned ah[2][4], am[2][4];
#pragma unroll
                for (int mi = 0; mi < 2; mi++)
#pragma unroll
                    for (int r = 0; r < 4; r++) {
                        int m = wm * 32 + mi * 16 + grp + (r & 1) * 8;
                        int cb = ks * 32 + tig * 4 + (r >> 1) * 16;
                        ah[mi][r] = *(const unsigned*)(sAh + m * 80 + cb);
                        am[mi][r] = *(const unsigned*)(sAm + m * 80 + cb);
                    }
#pragma unroll
                for (int ni = 0; ni < 8; ni++) {
                    unsigned bh[2], bm[2];
#pragma unroll
                    for (int r = 0; r < 2; r++) {
                        int n = wn * 64 + ni * 8 + grp;
                        int cb = ks * 32 + tig * 4 + r * 16;
                        bh[r] = *(const unsigned*)(sBh + n * 80 + cb);
                        bm[r] = *(const unsigned*)(sBm + n * 80 + cb);
                    }
#pragma unroll
                    for (int mi = 0; mi < 2; mi++) {
                        mma_bf16(acc[mi][ni], ah[mi], bh);
                        mma_bf16(acc[mi][ni], ah[mi], bm);
                        mma_bf16(acc[mi][ni], am[mi], bh);
                    }
                }
            }
            __syncthreads();
            if (pf) {
                char* da = sAh + lrow * 80 + lhk * 2;
                char* dm = sAm + lrow * 80 + lhk * 2;
                char* db = sBh + lrow * 80 + lhk * 2;
                char* dc = sBm + lrow * 80 + lhk * 2;
                *(uint4*)da = n0v; *(uint4*)(da + 16) = n1v;
                *(uint4*)dm = n2v; *(uint4*)(dm + 16) = n3v;
                *(uint4*)db = n4v; *(uint4*)(db + 16) = n5v;
                *(uint4*)dc = n6v; *(uint4*)(dc + 16) = n7v;
                __syncthreads();
            }
        }

        // ---- dump + scan, one 64-col half at a time (scs unions stages) ----
#pragma unroll
        for (int h = 0; h < 2; h++) {
            if (wn == h) {
#pragma unroll
                for (int mi = 0; mi < 2; mi++)
#pragma unroll
                    for (int ni = 0; ni < 8; ni++) {
                        int r0 = wm * 32 + mi * 16 + grp;
                        int c0 = ni * 8 + tig * 2;
                        scs[r0][c0]         = acc[mi][ni][0];
                        scs[r0][c0 + 1]     = acc[mi][ni][1];
                        scs[r0 + 8][c0]     = acc[mi][ni][2];
                        scs[r0 + 8][c0 + 1] = acc[mi][ni][3];
                    }
            }
            __syncthreads();
            {
                int token = tid >> 1;
                int cbase = (tid & 1) * 32;
#pragma unroll
                for (int s2 = 0; s2 < 32; s2++) {
                    int c = cbase + s2;
                    int j = jc + h * 64 + c;
                    if (j < jend) ins8(scs[token][c], j, tv8, ti8);
                }
            }
            __syncthreads();
        }
    }

    // ---- merge the 2 per-token partial top-8s -> split top-8 ----
    float* mval = (float*)smembuf;                 // [128][16]
    int*   midx = (int*)(smembuf + 128 * 16 * 4);  // [128][16]
    {
        int token = tid >> 1;
        int base = token * 16 + (tid & 1) * 8;
#pragma unroll
        for (int k = 0; k < 8; k++) { mval[base + k] = tv8[k]; midx[base + k] = ti8[k]; }
    }
    __syncthreads();
    if ((tid & 1) == 0) {
        int token = tid >> 1;
        float bv[8]; int bi[8];
#pragma unroll
        for (int k = 0; k < 8; k++) { bv[k] = -FLT_MAX; bi[k] = INT_MAX; }
#pragma unroll
        for (int c = 0; c < 16; c++)
            ins8(mval[token * 16 + c], midx[token * 16 + c], bv, bi);
        int* dst = cand + (size_t)(t0 + token) * NCAND + split * 8;
#pragma unroll
        for (int k = 0; k < 8; k++) dst[k] = bi[k];
    }
}

// ---------------- exact fp32 rescore of candidates -> top-4 + histogram ---
__global__ void rescore_k(const float* __restrict__ zi, const float* __restrict__ zc,
                          const int* __restrict__ cand)
{
    int t = (blockIdx.x * blockDim.x + threadIdx.x) >> 5;   // token (warp)
    int lane = threadIdx.x & 31;
    if (t >= NTOK) return;
    float a[8];
#pragma unroll
    for (int i = 0; i < 8; i++) a[i] = zi[(size_t)t * LDIM + lane + 32 * i];
    float tv[4] = {-FLT_MAX, -FLT_MAX, -FLT_MAX, -FLT_MAX};
    int   ti[4] = {INT_MAX, INT_MAX, INT_MAX, INT_MAX};
    for (int c = 0; c < NCAND; c++) {
        int j = cand[(size_t)t * NCAND + c];
        const float* b = zc + (size_t)j * LDIM;
        float s = 0.f;
#pragma unroll
        for (int i = 0; i < 8; i++) s += a[i] * b[lane + 32 * i];
#pragma unroll
        for (int off = 16; off > 0; off >>= 1)
            s += __shfl_xor_sync(0xFFFFFFFFu, s, off);
        ins4(s, j, tv, ti);
    }
    if (lane == 0) {
#pragma unroll
        for (int k = 0; k < 4; k++) {
            g_idx[t * 4 + k] = ti[k];
            atomicAdd(&g_counts[ti[k]], 1);
        }
    }
}

// ---------------- quantize -------------------------------------------------
__global__ void quant_k(const float* __restrict__ x, const float* __restrict__ cb,
                        float* __restrict__ out)
{
    int w = (blockIdx.x * blockDim.x + threadIdx.x) >> 5;   // token
    int lane = threadIdx.x & 31;
    if (w >= NTOK) return;
    const float* c0 = cb + (size_t)g_idx[w * 4 + 0] * DDIM;
    const float* c1 = cb + (size_t)g_idx[w * 4 + 1] * DDIM;
    const float* c2 = cb + (size_t)g_idx[w * 4 + 2] * DDIM;
    const float* c3 = cb + (size_t)g_idx[w * 4 + 3] * DDIM;
    double s = 0.0;
    for (int c = lane; c < DDIM; c += 32) {
        float qv = (((c0[c] + c1[c]) + c2[c]) + c3[c]) * 0.25f;
        float xv = x[(size_t)w * DDIM + c];
        float d = qv - xv;
        out[(size_t)w * DDIM + c] = xv + d;     // x + (q - x), matches STE
        g_q[(size_t)w * DDIM + c] = qv;
        s += (double)d * (double)d;
    }
#pragma unroll
    for (int off = 16; off > 0; off >>= 1)
        s += __shfl_down_sync(0xFFFFFFFFu, s, off);
    if (lane == 0) atomicAdd(&g_mse1, s);
}

// ---------------- entropy / usage ------------------------------------------
__global__ void ent_k()
{
    int i0 = blockIdx.x * blockDim.x + threadIdx.x;
    double e = 0.0; int nz = 0;
    for (int i = i0; i < VOC; i += gridDim.x * blockDim.x) {
        int c = g_counts[i];
        if (c > 0) {
            float p = (float)c * (1.0f / (NTOK * KSEL));
            e += (double)(p * logf(p + 1e-10f));
            nz++;
        }
    }
#pragma unroll
    for (int off = 16; off > 0; off >>= 1) {
        e  += __shfl_down_sync(0xFFFFFFFFu, e, off);
        nz += __shfl_down_sync(0xFFFFFFFFu, nz, off);
    }
    if ((threadIdx.x & 31) == 0) { atomicAdd(&g_ent, e); atomicAdd(&g_nz, nz); }
}

// ---------------- finalize scalars -----------------------------------------
__global__ void fin_k(float* __restrict__ out3)
{
    float lp = (float)(-g_ent);
    float mse1 = (float)(g_mse1 / ((double)NTOK * DDIM));
    float mse2 = (float)(g_mse2 / ((double)NTOK * LDIM));
    float loss = 1.25f * mse1 + 1.25f * mse2 + 0.1f * lp;
    out3[0] = loss;
    out3[1] = expf(lp);
    out3[2] = (float)g_nz / (float)VOC / (float)KSEL;
}

// ---------------- launch ----------------------------------------------------
static float* sym_f(const void* s) { void* p = nullptr; cudaGetSymbolAddress(&p, s); return (float*)p; }
static int*   sym_i(const void* s) { void* p = nullptr; cudaGetSymbolAddress(&p, s); return (int*)p; }
static __nv_bfloat16* sym_b(const void* s) { void* p = nullptr; cudaGetSymbolAddress(&p, s); return (__nv_bfloat16*)p; }

extern "C" void kernel_launch(void* const* d_in, const int* in_sizes, int n_in,
                              void* d_out, int out_size)
{
    const float* x  = (const float*)d_in[0];
    const float* cb = (const float*)d_in[1];
    const float* Wi = (const float*)d_in[2];
    const float* bi = (const float*)d_in[3];
    const float* Wc = (const float*)d_in[4];
    const float* bc = (const float*)d_in[5];
    float* out = (float*)d_out;

    float* zi_pre = sym_f(g_zi_pre);
    float* zi     = sym_f(g_zi);
    float* zc     = sym_f(g_zc);
    float* q      = sym_f(g_q);
    __nv_bfloat16* zih = sym_b(g_zih);
    __nv_bfloat16* zim = sym_b(g_zim);
    __nv_bfloat16* zch = sym_b(g_zch);
    __nv_bfloat16* zcm = sym_b(g_zcm);
    int* cand = sym_i(g_cand);

    init_k<<<64, 256>>>();
    // zi_pre = x @ W_in + b_in ; zi = l2n(zi_pre)
    gemm_k<0><<<dim3(NTOK / 64, LDIM / 64), 256>>>(x, Wi, bi, zi_pre, nullptr, NTOK);
    norm_k<<<NTOK / 8, 256>>>(zi_pre, zi, NTOK);
    // zc = l2n(codebook @ W_code + b_code)
    gemm_k<0><<<dim3((VOC + 63) / 64, LDIM / 64), 256>>>(cb, Wc, bc, zc, nullptr, VOC);
    norm_k<<<(VOC + 7) / 8, 256>>>(zc, zc, VOC);
    // bf16 splits
    split_k<<<512, 256>>>(zi, zih, zim, NTOK * LDIM);
    split_k<<<2048, 256>>>(zc, zch, zcm, VOC * LDIM);
    // tensor-core approx scores + per-split top-8 candidates
    topk_mma<<<dim3(NTOK / 128, NSPLIT), 256>>>(zih, zim, zch, zcm, cand);
    // exact fp32 rescore -> final top-4 + histogram
    rescore_k<<<NTOK / 8, 256>>>(zi, zc, cand);
    // quantize + STE output + mse1
    quant_k<<<NTOK / 8, 256>>>(x, cb, out);
    // mse2 = sum((q @ W_code + b_code - zi_pre)^2)
    gemm_k<1><<<dim3(NTOK / 64, LDIM / 64), 256>>>(q, Wc, bc, nullptr, zi_pre, NTOK);
    ent_k<<<64, 256>>>();
    fin_k<<<1, 1>>>(out + (size_t)NTOK * DDIM);
}

// round 4
// speedup vs baseline: 2.9249x; 1.6117x over previous
#include <cuda_runtime.h>
#include <cuda_bf16.h>
#include <math.h>
#include <float.h>
#include <limits.h>

// Problem constants
#define NTOK 4096      // B*S
#define DDIM 768
#define LDIM 256
#define VOC  50265
#define KSEL 4
#define NSPLIT 9
#define SPLIT_SZ 5585  // 9*5585 == 50265 exactly
#define NCAND (NSPLIT * 8)   // 72 candidates per token

// ---------------- scratch (device globals; no allocations) ----------------
__device__ float  g_zi_pre[NTOK * LDIM];      // x@W_in+b (kept for mse2 ref)
__device__ float  g_zi[NTOK * LDIM];          // normalized
__device__ float  g_zc[VOC * LDIM];           // codebook@W_code+b, normalized
__device__ float  g_q[NTOK * DDIM];           // quantized
__device__ __nv_bfloat16 g_zih[NTOK * LDIM];
__device__ __nv_bfloat16 g_zch[VOC * LDIM];
__device__ int    g_cand[NTOK * NCAND];
__device__ int    g_idx[NTOK * KSEL];
__device__ int    g_counts[VOC];
__device__ double g_mse1, g_mse2, g_ent;
__device__ int    g_nz;

// ---------------- topk helpers ----------------
__device__ __forceinline__ bool better(float v, int j, float v2, int j2) {
    return (v > v2) || (v == v2 && j < j2);
}
__device__ __forceinline__ void ins4(float v, int j, float tv[4], int ti[4]) {
    if (!better(v, j, tv[3], ti[3])) return;
    tv[3] = v; ti[3] = j;
#pragma unroll
    for (int k = 3; k > 0; k--) {
        if (better(tv[k], ti[k], tv[k-1], ti[k-1])) {
            float fv = tv[k]; tv[k] = tv[k-1]; tv[k-1] = fv;
            int   fi = ti[k]; ti[k] = ti[k-1]; ti[k-1] = fi;
        }
    }
}
__device__ __forceinline__ void ins8(float v, int j, float tv[8], int ti[8]) {
    if (!better(v, j, tv[7], ti[7])) return;
    tv[7] = v; ti[7] = j;
#pragma unroll
    for (int k = 7; k > 0; k--) {
        if (better(tv[k], ti[k], tv[k-1], ti[k-1])) {
            float fv = tv[k]; tv[k] = tv[k-1]; tv[k-1] = fv;
            int   fi = ti[k]; ti[k] = ti[k-1]; ti[k-1] = fi;
        }
    }
}

// ---------------- bf16 mma helper ----------------
__device__ __forceinline__ void mma_bf16(float d[4], const unsigned a[4], const unsigned b[2]) {
    asm("mma.sync.aligned.m16n8k16.row.col.f32.bf16.bf16.f32 "
        "{%0,%1,%2,%3},{%4,%5,%6,%7},{%8,%9},{%0,%1,%2,%3};"
        : "+f"(d[0]), "+f"(d[1]), "+f"(d[2]), "+f"(d[3])
        : "r"(a[0]), "r"(a[1]), "r"(a[2]), "r"(a[3]), "r"(b[0]), "r"(b[1]));
}

// ---------------- init ----------------
__global__ void init_k() {
    int i = blockIdx.x * blockDim.x + threadIdx.x;
    for (int v = i; v < VOC; v += gridDim.x * blockDim.x) g_counts[v] = 0;
    if (i == 0) { g_mse1 = 0.0; g_mse2 = 0.0; g_ent = 0.0; g_nz = 0; }
}

// ---------------- GEMM (R1 proven): C[M,256] = A[M,768] @ W + bias --------
template <int MODE>
__global__ void __launch_bounds__(256, 2)
gemm_k(const float* __restrict__ A, const float* __restrict__ W,
       const float* __restrict__ bias, float* __restrict__ C,
       const float* __restrict__ ref, int M)
{
    __shared__ float As[32][68];   // k-major: As[k][m]
    __shared__ float Ws[32][68];   // Ws[k][n]
    const int tid = threadIdx.x;
    const int m0 = blockIdx.x * 64, n0 = blockIdx.y * 64;
    const int tx = tid & 15, ty = tid >> 4;

    float acc[4][4] = {};
    for (int c0 = 0; c0 < DDIM; c0 += 32) {
#pragma unroll
        for (int t = 0; t < 2; t++) {            // A tile -> transposed store
            int li = tid * 2 + t;
            int row = li >> 3, kq = li & 7;
            float4 v = make_float4(0.f, 0.f, 0.f, 0.f);
            if (m0 + row < M)
                v = *(const float4*)&A[(size_t)(m0 + row) * DDIM + c0 + kq * 4];
            As[kq*4+0][row] = v.x; As[kq*4+1][row] = v.y;
            As[kq*4+2][row] = v.z; As[kq*4+3][row] = v.w;
        }
#pragma unroll
        for (int t = 0; t < 2; t++) {            // W tile -> direct store
            int li = tid * 2 + t;
            int r = li >> 4, nq = li & 15;
            float4 v = *(const float4*)&W[(size_t)(c0 + r) * LDIM + n0 + nq * 4];
            *(float4*)&Ws[r][nq * 4] = v;
        }
        __syncthreads();
#pragma unroll
        for (int kk = 0; kk < 32; kk++) {
            float4 a4 = *(float4*)&As[kk][ty * 4];
            float4 b4 = *(float4*)&Ws[kk][tx * 4];
            float av[4] = {a4.x, a4.y, a4.z, a4.w};
            float bv[4] = {b4.x, b4.y, b4.z, b4.w};
#pragma unroll
            for (int i = 0; i < 4; i++)
#pragma unroll
                for (int j = 0; j < 4; j++)
                    acc[i][j] += av[i] * bv[j];
        }
        __syncthreads();
    }

    if (MODE == 0) {
#pragma unroll
        for (int i = 0; i < 4; i++) {
            int row = m0 + ty * 4 + i;
            if (row < M) {
#pragma unroll
                for (int j = 0; j < 4; j++) {
                    int col = n0 + tx * 4 + j;
                    C[(size_t)row * LDIM + col] = acc[i][j] + bias[col];
                }
            }
        }
    } else {
        double s = 0.0;
#pragma unroll
        for (int i = 0; i < 4; i++) {
            int row = m0 + ty * 4 + i;
            if (row < M) {
#pragma unroll
                for (int j = 0; j < 4; j++) {
                    int col = n0 + tx * 4 + j;
                    float cv = acc[i][j] + bias[col];
                    float d  = cv - ref[(size_t)row * LDIM + col];
                    s += (double)d * (double)d;
                }
            }
        }
#pragma unroll
        for (int off = 16; off > 0; off >>= 1)
            s += __shfl_down_sync(0xFFFFFFFFu, s, off);
        if ((tid & 31) == 0) atomicAdd(&g_mse2, s);
    }
}

// ---------------- row L2-normalize, fused bf16 emit ------------------------
__global__ void norm_k(const float* __restrict__ in, float* __restrict__ out,
                       __nv_bfloat16* __restrict__ outh, int M)
{
    int w = (blockIdx.x * blockDim.x + threadIdx.x) >> 5;
    int lane = threadIdx.x & 31;
    if (w >= M) return;
    const float* r = in + (size_t)w * LDIM;
    float vals[8];
    float s = 0.f;
#pragma unroll
    for (int i = 0; i < 8; i++) { vals[i] = r[lane + 32 * i]; s += vals[i] * vals[i]; }
#pragma unroll
    for (int off = 16; off > 0; off >>= 1)
        s += __shfl_xor_sync(0xFFFFFFFFu, s, off);
    float t = s + 1e-12f;
    float sc = rsqrtf(t);
    sc = sc * (1.5f - 0.5f * t * sc * sc);   // Newton: ~1 ulp
    float* o = out + (size_t)w * LDIM;
    __nv_bfloat16* oh = outh + (size_t)w * LDIM;
#pragma unroll
    for (int i = 0; i < 8; i++) {
        float v = vals[i] * sc;
        o[lane + 32 * i] = v;
        oh[lane + 32 * i] = __float2bfloat16(v);
    }
}

// ---------------- tensor-core approx scores + top-8 candidates ------------
// grid (NTOK/128, NSPLIT). Tile 128 tokens x 128 codes, single bf16 product.
// k staged in 32-dim double-buffered stages (gmem -> smem while MMA runs).
// Input-rounding error ~2e-4 << selection margins; exact rescore downstream.
__global__ void __launch_bounds__(256, 2)
topk_mma(const __nv_bfloat16* __restrict__ zih, const __nv_bfloat16* __restrict__ zch,
         int* __restrict__ cand)
{
    // 4 stage buffers (A0,A1,B0,B1; 128 rows x 80B, 64B data) union scs[128][68]
    __shared__ __align__(16) char smembuf[40960];
    float (*scs)[68] = (float(*)[68])smembuf;

    const int tid = threadIdx.x;
    const int w = tid >> 5, lane = tid & 31;
    const int grp = lane >> 2, tig = lane & 3;
    const int wm = w >> 1, wn = w & 1;            // 4 x 2 warp grid
    const int t0 = blockIdx.x * 128;
    const int split = blockIdx.y;
    const int j0 = split * SPLIT_SZ;
    const int jend = j0 + SPLIT_SZ;

    const int lrow = tid >> 1;                    // loader row 0..127
    const int eo   = (tid & 1) * 16;              // element offset in 32-elem row

    char* bufA0 = smembuf;
    char* bufA1 = smembuf + 10240;
    char* bufB0 = smembuf + 20480;
    char* bufB1 = smembuf + 30720;

    float tv8[8]; int ti8[8];
#pragma unroll
    for (int k = 0; k < 8; k++) { tv8[k] = -FLT_MAX; ti8[k] = INT_MAX; }

    for (int jc = j0; jc < jend; jc += 128) {
        float acc[2][8][4] = {};
        int jrow = jc + lrow;
        bool bok = (jrow < jend);
        const __nv_bfloat16* arow = zih + (size_t)(t0 + lrow) * LDIM + eo;
        const __nv_bfloat16* brow = zch + (size_t)jrow * LDIM + eo;

        // ---- prologue: stage 0 gmem -> smem ----
        {
            uint4 a0 = *(const uint4*)(arow);
            uint4 a1 = *(const uint4*)(arow + 8);
            uint4 b0 = {0,0,0,0}, b1 = {0,0,0,0};
            if (bok) { b0 = *(const uint4*)(brow); b1 = *(const uint4*)(brow + 8); }
            char* da = bufA0 + lrow * 80 + eo * 2;
            char* db = bufB0 + lrow * 80 + eo * 2;
            *(uint4*)da = a0; *(uint4*)(da + 16) = a1;
            *(uint4*)db = b0; *(uint4*)(db + 16) = b1;
        }

#pragma unroll
        for (int s = 0; s < 8; s++) {            // 8 stages of 32 k-dims
            __syncthreads();
            uint4 na0, na1, nb0, nb1;
            bool pf = (s < 7);
            if (pf) {                            // prefetch next stage
                int ko = (s + 1) * 32;
                na0 = *(const uint4*)(arow + ko);
                na1 = *(const uint4*)(arow + ko + 8);
                uint4 z = {0,0,0,0}; nb0 = z; nb1 = z;
                if (bok) {
                    nb0 = *(const uint4*)(brow + ko);
                    nb1 = *(const uint4*)(brow + ko + 8);
                }
            }
            char* sA = (s & 1) ? bufA1 : bufA0;
            char* sB = (s & 1) ? bufB1 : bufB0;
#pragma unroll
            for (int ks = 0; ks < 2; ks++) {
                unsigned ah[2][4];
#pragma unroll
                for (int mi = 0; mi < 2; mi++)
#pragma unroll
                    for (int r = 0; r < 4; r++) {
                        int m = wm * 32 + mi * 16 + grp + (r & 1) * 8;
                        int cb = ks * 32 + tig * 4 + (r >> 1) * 16;
                        ah[mi][r] = *(const unsigned*)(sA + m * 80 + cb);
                    }
#pragma unroll
                for (int ni = 0; ni < 8; ni++) {
                    unsigned bh[2];
#pragma unroll
                    for (int r = 0; r < 2; r++) {
                        int n = wn * 64 + ni * 8 + grp;
                        int cb = ks * 32 + tig * 4 + r * 16;
                        bh[r] = *(const unsigned*)(sB + n * 80 + cb);
                    }
                    mma_bf16(acc[0][ni], ah[0], bh);
                    mma_bf16(acc[1][ni], ah[1], bh);
                }
            }
            if (pf) {
                char* da = ((s & 1) ? bufA0 : bufA1) + lrow * 80 + eo * 2;
                char* db = ((s & 1) ? bufB0 : bufB1) + lrow * 80 + eo * 2;
                *(uint4*)da = na0; *(uint4*)(da + 16) = na1;
                *(uint4*)db = nb0; *(uint4*)(db + 16) = nb1;
            }
        }
        __syncthreads();

        // ---- dump + scan, one 64-col half at a time ----
#pragma unroll
        for (int h = 0; h < 2; h++) {
            if (wn == h) {
#pragma unroll
                for (int mi = 0; mi < 2; mi++)
#pragma unroll
                    for (int ni = 0; ni < 8; ni++) {
                        int r0 = wm * 32 + mi * 16 + grp;
                        int c0 = ni * 8 + tig * 2;
                        scs[r0][c0]         = acc[mi][ni][0];
                        scs[r0][c0 + 1]     = acc[mi][ni][1];
                        scs[r0 + 8][c0]     = acc[mi][ni][2];
                        scs[r0 + 8][c0 + 1] = acc[mi][ni][3];
                    }
            }
            __syncthreads();
            {
                int token = tid >> 1;
                int cb0 = (tid & 1) * 32;
                int jb = jc + h * 64 + cb0;
#pragma unroll
                for (int s2 = 0; s2 < 8; s2++) {
                    float4 v4 = *(float4*)&scs[token][cb0 + s2 * 4];
                    int j = jb + s2 * 4;
                    if (j     < jend && v4.x >= tv8[7]) ins8(v4.x, j,     tv8, ti8);
                    if (j + 1 < jend && v4.y >= tv8[7]) ins8(v4.y, j + 1, tv8, ti8);
                    if (j + 2 < jend && v4.z >= tv8[7]) ins8(v4.z, j + 2, tv8, ti8);
                    if (j + 3 < jend && v4.w >= tv8[7]) ins8(v4.w, j + 3, tv8, ti8);
                }
            }
            __syncthreads();
        }
    }

    // ---- merge the 2 per-token partial top-8s -> split top-8 ----
    float* mval = (float*)smembuf;                 // [128][16]
    int*   midx = (int*)(smembuf + 128 * 16 * 4);  // [128][16]
    {
        int token = tid >> 1;
        int base = token * 16 + (tid & 1) * 8;
#pragma unroll
        for (int k = 0; k < 8; k++) { mval[base + k] = tv8[k]; midx[base + k] = ti8[k]; }
    }
    __syncthreads();
    if ((tid & 1) == 0) {
        int token = tid >> 1;
        float bv[8]; int bi[8];
#pragma unroll
        for (int k = 0; k < 8; k++) { bv[k] = -FLT_MAX; bi[k] = INT_MAX; }
#pragma unroll
        for (int c = 0; c < 16; c++)
            ins8(mval[token * 16 + c], midx[token * 16 + c], bv, bi);
        int* dst = cand + (size_t)(t0 + token) * NCAND + split * 8;
#pragma unroll
        for (int k = 0; k < 8; k++) dst[k] = bi[k];
    }
}

// ---------------- exact fp32 rescore of candidates -> top-4 + histogram ---
__global__ void rescore_k(const float* __restrict__ zi, const float* __restrict__ zc,
                          const int* __restrict__ cand)
{
    int t = (blockIdx.x * blockDim.x + threadIdx.x) >> 5;   // token (warp)
    int lane = threadIdx.x & 31;
    if (t >= NTOK) return;
    float a[8];
#pragma unroll
    for (int i = 0; i < 8; i++) a[i] = zi[(size_t)t * LDIM + lane + 32 * i];
    float tv[4] = {-FLT_MAX, -FLT_MAX, -FLT_MAX, -FLT_MAX};
    int   ti[4] = {INT_MAX, INT_MAX, INT_MAX, INT_MAX};
    for (int c = 0; c < NCAND; c += 2) {
        int j0c = cand[(size_t)t * NCAND + c];
        int j1c = cand[(size_t)t * NCAND + c + 1];
        const float* b0 = zc + (size_t)j0c * LDIM;
        const float* b1 = zc + (size_t)j1c * LDIM;
        float s0 = 0.f, s1 = 0.f;
#pragma unroll
        for (int i = 0; i < 8; i++) {
            s0 += a[i] * b0[lane + 32 * i];
            s1 += a[i] * b1[lane + 32 * i];
        }
#pragma unroll
        for (int off = 16; off > 0; off >>= 1) {
            s0 += __shfl_xor_sync(0xFFFFFFFFu, s0, off);
            s1 += __shfl_xor_sync(0xFFFFFFFFu, s1, off);
        }
        ins4(s0, j0c, tv, ti);
        ins4(s1, j1c, tv, ti);
    }
    if (lane == 0) {
#pragma unroll
        for (int k = 0; k < 4; k++) {
            g_idx[t * 4 + k] = ti[k];
            atomicAdd(&g_counts[ti[k]], 1);
        }
    }
}

// ---------------- quantize -------------------------------------------------
__global__ void quant_k(const float* __restrict__ x, const float* __restrict__ cb,
                        float* __restrict__ out)
{
    int w = (blockIdx.x * blockDim.x + threadIdx.x) >> 5;   // token
    int lane = threadIdx.x & 31;
    if (w >= NTOK) return;
    const float* c0 = cb + (size_t)g_idx[w * 4 + 0] * DDIM;
    const float* c1 = cb + (size_t)g_idx[w * 4 + 1] * DDIM;
    const float* c2 = cb + (size_t)g_idx[w * 4 + 2] * DDIM;
    const float* c3 = cb + (size_t)g_idx[w * 4 + 3] * DDIM;
    double s = 0.0;
    for (int c = lane; c < DDIM; c += 32) {
        float qv = (((c0[c] + c1[c]) + c2[c]) + c3[c]) * 0.25f;
        float xv = x[(size_t)w * DDIM + c];
        float d = qv - xv;
        out[(size_t)w * DDIM + c] = xv + d;     // x + (q - x), matches STE
        g_q[(size_t)w * DDIM + c] = qv;
        s += (double)d * (double)d;
    }
#pragma unroll
    for (int off = 16; off > 0; off >>= 1)
        s += __shfl_down_sync(0xFFFFFFFFu, s, off);
    if (lane == 0) atomicAdd(&g_mse1, s);
}

// ---------------- entropy / usage ------------------------------------------
__global__ void ent_k()
{
    int i0 = blockIdx.x * blockDim.x + threadIdx.x;
    double e = 0.0; int nz = 0;
    for (int i = i0; i < VOC; i += gridDim.x * blockDim.x) {
        int c = g_counts[i];
        if (c > 0) {
            float p = (float)c * (1.0f / (NTOK * KSEL));
            e += (double)(p * logf(p + 1e-10f));
            nz++;
        }
    }
#pragma unroll
    for (int off = 16; off > 0; off >>= 1) {
        e  += __shfl_down_sync(0xFFFFFFFFu, e, off);
        nz += __shfl_down_sync(0xFFFFFFFFu, nz, off);
    }
    if ((threadIdx.x & 31) == 0) { atomicAdd(&g_ent, e); atomicAdd(&g_nz, nz); }
}

// ---------------- finalize scalars -----------------------------------------
__global__ void fin_k(float* __restrict__ out3)
{
    float lp = (float)(-g_ent);
    float mse1 = (float)(g_mse1 / ((double)NTOK * DDIM));
    float mse2 = (float)(g_mse2 / ((double)NTOK * LDIM));
    float loss = 1.25f * mse1 + 1.25f * mse2 + 0.1f * lp;
    out3[0] = loss;
    out3[1] = expf(lp);
    out3[2] = (float)g_nz / (float)VOC / (float)KSEL;
}

// ---------------- launch ----------------------------------------------------
static float* sym_f(const void* s) { void* p = nullptr; cudaGetSymbolAddress(&p, s); return (float*)p; }
static int*   sym_i(const void* s) { void* p = nullptr; cudaGetSymbolAddress(&p, s); return (int*)p; }
static __nv_bfloat16* sym_b(const void* s) { void* p = nullptr; cudaGetSymbolAddress(&p, s); return (__nv_bfloat16*)p; }

extern "C" void kernel_launch(void* const* d_in, const int* in_sizes, int n_in,
                              void* d_out, int out_size)
{
    const float* x  = (const float*)d_in[0];
    const float* cb = (const float*)d_in[1];
    const float* Wi = (const float*)d_in[2];
    const float* bi = (const float*)d_in[3];
    const float* Wc = (const float*)d_in[4];
    const float* bc = (const float*)d_in[5];
    float* out = (float*)d_out;

    float* zi_pre = sym_f(g_zi_pre);
    float* zi     = sym_f(g_zi);
    float* zc     = sym_f(g_zc);
    float* q      = sym_f(g_q);
    __nv_bfloat16* zih = sym_b(g_zih);
    __nv_bfloat16* zch = sym_b(g_zch);
    int* cand = sym_i(g_cand);

    init_k<<<64, 256>>>();
    // zi_pre = x @ W_in + b_in ; zi = l2n(zi_pre) (+ bf16 copy)
    gemm_k<0><<<dim3(NTOK / 64, LDIM / 64), 256>>>(x, Wi, bi, zi_pre, nullptr, NTOK);
    norm_k<<<NTOK / 8, 256>>>(zi_pre, zi, zih, NTOK);
    // zc = l2n(codebook @ W_code + b_code) (+ bf16 copy)
    gemm_k<0><<<dim3((VOC + 63) / 64, LDIM / 64), 256>>>(cb, Wc, bc, zc, nullptr, VOC);
    norm_k<<<(VOC + 7) / 8, 256>>>(zc, zc, zch, VOC);
    // tensor-core approx scores (single bf16 product) + per-split top-8
    topk_mma<<<dim3(NTOK / 128, NSPLIT), 256>>>(zih, zch, cand);
    // exact fp32 rescore -> final top-4 + histogram
    rescore_k<<<NTOK / 8, 256>>>(zi, zc, cand);
    // quantize + STE output + mse1
    quant_k<<<NTOK / 8, 256>>>(x, cb, out);
    // mse2 = sum((q @ W_code + b_code - zi_pre)^2)
    gemm_k<1><<<dim3(NTOK / 64, LDIM / 64), 256>>>(q, Wc, bc, nullptr, zi_pre, NTOK);
    ent_k<<<64, 256>>>();
    fin_k<<<1, 1>>>(out + (size_t)NTOK * DDIM);
}

// round 7
// speedup vs baseline: 4.2152x; 1.4411x over previous
#include <cuda_runtime.h>
#include <cuda_bf16.h>
#include <math.h>
#include <float.h>
#include <limits.h>

// Problem constants
#define NTOK 4096      // B*S
#define DDIM 768
#define LDIM 256
#define VOC  50265
#define VOCP 50304     // 393 tiles of 128
#define NBLK 786       // 64-code blocks (VOCP/64)
#define BMAXP 788      // padded row
#define KSEL 4
#define NCAND 24

// ---------------- scratch (device globals; no allocations) ----------------
__device__ float  g_zi_pre[NTOK * LDIM];      // x@W_in+b (kept for mse2 ref)
__device__ float  g_zi[NTOK * LDIM];          // normalized
__device__ float  g_zc[VOC * LDIM];           // codebook@W_code+b, normalized
__device__ float  g_q[NTOK * DDIM];           // quantized
__device__ __nv_bfloat16 g_zih[NTOK * LDIM];
__device__ __nv_bfloat16 g_zch[VOC * LDIM];
__device__ __nv_bfloat16 g_scores[(size_t)NTOK * VOCP];   // all approx scores
__device__ __nv_bfloat16 g_bmax[(size_t)NTOK * BMAXP];    // per-64-block max
__device__ int    g_idx[NTOK * KSEL];
__device__ int    g_counts[VOC];
__device__ double g_mse1, g_mse2, g_ent;
__device__ int    g_nz;

// ---------------- topk helpers ----------------
__device__ __forceinline__ bool better(float v, int j, float v2, int j2) {
    return (v > v2) || (v == v2 && j < j2);
}
template <int K>
__device__ __forceinline__ void insK(float v, int j, float tv[K], int ti[K]) {
    if (!better(v, j, tv[K-1], ti[K-1])) return;
    tv[K-1] = v; ti[K-1] = j;
#pragma unroll
    for (int k = K-1; k > 0; k--) {
        if (better(tv[k], ti[k], tv[k-1], ti[k-1])) {
            float fv = tv[k]; tv[k] = tv[k-1]; tv[k-1] = fv;
            int   fi = ti[k]; ti[k] = ti[k-1]; ti[k-1] = fi;
        }
    }
}

// ---------------- bf16 mma helper ----------------
__device__ __forceinline__ void mma_bf16(float d[4], const unsigned a[4], const unsigned b[2]) {
    asm("mma.sync.aligned.m16n8k16.row.col.f32.bf16.bf16.f32 "
        "{%0,%1,%2,%3},{%4,%5,%6,%7},{%8,%9},{%0,%1,%2,%3};"
        : "+f"(d[0]), "+f"(d[1]), "+f"(d[2]), "+f"(d[3])
        : "r"(a[0]), "r"(a[1]), "r"(a[2]), "r"(a[3]), "r"(b[0]), "r"(b[1]));
}

// ---------------- init ----------------
__global__ void init_k() {
    int i = blockIdx.x * blockDim.x + threadIdx.x;
    for (int v = i; v < VOC; v += gridDim.x * blockDim.x) g_counts[v] = 0;
    if (i == 0) { g_mse1 = 0.0; g_mse2 = 0.0; g_ent = 0.0; g_nz = 0; }
}

// ---------------- GEMM (R1 proven): C[M,256] = A[M,768] @ W + bias --------
template <int MODE>
__global__ void __launch_bounds__(256, 2)
gemm_k(const float* __restrict__ A, const float* __restrict__ W,
       const float* __restrict__ bias, float* __restrict__ C,
       const float* __restrict__ ref, int M)
{
    __shared__ float As[32][68];   // k-major: As[k][m]
    __shared__ float Ws[32][68];   // Ws[k][n]
    const int tid = threadIdx.x;
    const int m0 = blockIdx.x * 64, n0 = blockIdx.y * 64;
    const int tx = tid & 15, ty = tid >> 4;

    float acc[4][4] = {};
    for (int c0 = 0; c0 < DDIM; c0 += 32) {
#pragma unroll
        for (int t = 0; t < 2; t++) {            // A tile -> transposed store
            int li = tid * 2 + t;
            int row = li >> 3, kq = li & 7;
            float4 v = make_float4(0.f, 0.f, 0.f, 0.f);
            if (m0 + row < M)
                v = *(const float4*)&A[(size_t)(m0 + row) * DDIM + c0 + kq * 4];
            As[kq*4+0][row] = v.x; As[kq*4+1][row] = v.y;
            As[kq*4+2][row] = v.z; As[kq*4+3][row] = v.w;
        }
#pragma unroll
        for (int t = 0; t < 2; t++) {            // W tile -> direct store
            int li = tid * 2 + t;
            int r = li >> 4, nq = li & 15;
            float4 v = *(const float4*)&W[(size_t)(c0 + r) * LDIM + n0 + nq * 4];
            *(float4*)&Ws[r][nq * 4] = v;
        }
        __syncthreads();
#pragma unroll
        for (int kk = 0; kk < 32; kk++) {
            float4 a4 = *(float4*)&As[kk][ty * 4];
            float4 b4 = *(float4*)&Ws[kk][tx * 4];
            float av[4] = {a4.x, a4.y, a4.z, a4.w};
            float bv[4] = {b4.x, b4.y, b4.z, b4.w};
#pragma unroll
            for (int i = 0; i < 4; i++)
#pragma unroll
                for (int j = 0; j < 4; j++)
                    acc[i][j] += av[i] * bv[j];
        }
        __syncthreads();
    }

    if (MODE == 0) {
#pragma unroll
        for (int i = 0; i < 4; i++) {
            int row = m0 + ty * 4 + i;
            if (row < M) {
#pragma unroll
                for (int j = 0; j < 4; j++) {
                    int col = n0 + tx * 4 + j;
                    C[(size_t)row * LDIM + col] = acc[i][j] + bias[col];
                }
            }
        }
    } else {
        double s = 0.0;
#pragma unroll
        for (int i = 0; i < 4; i++) {
            int row = m0 + ty * 4 + i;
            if (row < M) {
#pragma unroll
                for (int j = 0; j < 4; j++) {
                    int col = n0 + tx * 4 + j;
                    float cv = acc[i][j] + bias[col];
                    float d  = cv - ref[(size_t)row * LDIM + col];
                    s += (double)d * (double)d;
                }
            }
        }
#pragma unroll
        for (int off = 16; off > 0; off >>= 1)
            s += __shfl_down_sync(0xFFFFFFFFu, s, off);
        if ((tid & 31) == 0) atomicAdd(&g_mse2, s);
    }
}

// ---------------- row L2-normalize, fused bf16 emit ------------------------
__global__ void norm_k(const float* __restrict__ in, float* __restrict__ out,
                       __nv_bfloat16* __restrict__ outh, int M)
{
    int w = (blockIdx.x * blockDim.x + threadIdx.x) >> 5;
    int lane = threadIdx.x & 31;
    if (w >= M) return;
    const float* r = in + (size_t)w * LDIM;
    float vals[8];
    float s = 0.f;
#pragma unroll
    for (int i = 0; i < 8; i++) { vals[i] = r[lane + 32 * i]; s += vals[i] * vals[i]; }
#pragma unroll
    for (int off = 16; off > 0; off >>= 1)
        s += __shfl_xor_sync(0xFFFFFFFFu, s, off);
    float t = s + 1e-12f;
    float sc = rsqrtf(t);
    sc = sc * (1.5f - 0.5f * t * sc * sc);   // Newton: ~1 ulp
    float* o = out + (size_t)w * LDIM;
    __nv_bfloat16* oh = outh + (size_t)w * LDIM;
#pragma unroll
    for (int i = 0; i < 8; i++) {
        float v = vals[i] * sc;
        o[lane + 32 * i] = v;
        oh[lane + 32 * i] = __float2bfloat16(v);
    }
}

// ---------------- K1: MMA scores -> bf16 store + 64-block max --------------
// grid (NTOK/128, VOCP/128). No score scan — just cvt, store, packed max.
__global__ void __launch_bounds__(256, 2)
score_mma(const __nv_bfloat16* __restrict__ zih, const __nv_bfloat16* __restrict__ zch,
          __nv_bfloat16* __restrict__ scores, __nv_bfloat16* __restrict__ bmax)
{
    __shared__ __align__(16) char smembuf[40960];
    const int tid = threadIdx.x;
    const int w = tid >> 5, lane = tid & 31;
    const int grp = lane >> 2, tig = lane & 3;
    const int wm = w >> 1, wn = w & 1;            // 4 x 2 warp grid
    const int t0 = blockIdx.x * 128;
    const int jc = blockIdx.y * 128;

    const int lrow = tid >> 1;                    // loader row 0..127
    const int eo   = (tid & 1) * 16;

    char* bufA0 = smembuf;
    char* bufA1 = smembuf + 10240;
    char* bufB0 = smembuf + 20480;
    char* bufB1 = smembuf + 30720;

    float acc[2][8][4] = {};
    int jrow = jc + lrow;
    bool bok = (jrow < VOC);
    const __nv_bfloat16* arow = zih + (size_t)(t0 + lrow) * LDIM + eo;
    const __nv_bfloat16* brow = zch + (size_t)jrow * LDIM + eo;

    // prologue: stage 0
    {
        uint4 a0 = *(const uint4*)(arow);
        uint4 a1 = *(const uint4*)(arow + 8);
        uint4 b0 = {0,0,0,0}, b1 = {0,0,0,0};
        if (bok) { b0 = *(const uint4*)(brow); b1 = *(const uint4*)(brow + 8); }
        char* da = bufA0 + lrow * 80 + eo * 2;
        char* db = bufB0 + lrow * 80 + eo * 2;
        *(uint4*)da = a0; *(uint4*)(da + 16) = a1;
        *(uint4*)db = b0; *(uint4*)(db + 16) = b1;
    }

#pragma unroll
    for (int s = 0; s < 8; s++) {            // 8 stages of 32 k-dims
        __syncthreads();
        uint4 na0, na1, nb0, nb1;
        bool pf = (s < 7);
        if (pf) {
            int ko = (s + 1) * 32;
            na0 = *(const uint4*)(arow + ko);
            na1 = *(const uint4*)(arow + ko + 8);
            uint4 z = {0,0,0,0}; nb0 = z; nb1 = z;
            if (bok) {
                nb0 = *(const uint4*)(brow + ko);
                nb1 = *(const uint4*)(brow + ko + 8);
            }
        }
        char* sA = (s & 1) ? bufA1 : bufA0;
        char* sB = (s & 1) ? bufB1 : bufB0;
#pragma unroll
        for (int ks = 0; ks < 2; ks++) {
            unsigned ah[2][4];
#pragma unroll
            for (int mi = 0; mi < 2; mi++)
#pragma unroll
                for (int r = 0; r < 4; r++) {
                    int m = wm * 32 + mi * 16 + grp + (r & 1) * 8;
                    int cb = ks * 32 + tig * 4 + (r >> 1) * 16;
                    ah[mi][r] = *(const unsigned*)(sA + m * 80 + cb);
                }
#pragma unroll
            for (int ni = 0; ni < 8; ni++) {
                unsigned bh[2];
#pragma unroll
                for (int r = 0; r < 2; r++) {
                    int n = wn * 64 + ni * 8 + grp;
                    int cb = ks * 32 + tig * 4 + r * 16;
                    bh[r] = *(const unsigned*)(sB + n * 80 + cb);
                }
                mma_bf16(acc[0][ni], ah[0], bh);
                mma_bf16(acc[1][ni], ah[1], bh);
            }
        }
        if (pf) {
            char* da = ((s & 1) ? bufA0 : bufA1) + lrow * 80 + eo * 2;
            char* db = ((s & 1) ? bufB0 : bufB1) + lrow * 80 + eo * 2;
            *(uint4*)da = na0; *(uint4*)(da + 16) = na1;
            *(uint4*)db = nb0; *(uint4*)(db + 16) = nb1;
        }
    }

    // ---- epilogue: cvt bf16, store, packed block-max (no syncs needed) ----
    const int colbase = wn * 64 + tig * 2;
#pragma unroll
    for (int mi = 0; mi < 2; mi++)
#pragma unroll
    for (int h = 0; h < 2; h++) {
        int row_l = wm * 32 + mi * 16 + grp + h * 8;
        size_t rowoff = (size_t)(t0 + row_l) * VOCP;
        unsigned p[8];
#pragma unroll
        for (int ni = 0; ni < 8; ni++) {
            float2 f2 = make_float2(acc[mi][ni][2*h], acc[mi][ni][2*h + 1]);
            __nv_bfloat162 bb = __float22bfloat162_rn(f2);   // .x -> low half
            p[ni] = *(unsigned*)&bb;
        }
        if (jc + 128 > VOC) {        // mask tail columns with bf16 -inf
#pragma unroll
            for (int ni = 0; ni < 8; ni++) {
                int j = jc + colbase + ni * 8;
                if (j >= VOC)     p[ni] = (p[ni] & 0xFFFF0000u) | 0x0000FF80u;
                if (j + 1 >= VOC) p[ni] = (p[ni] & 0x0000FFFFu) | 0xFF800000u;
            }
        }
#pragma unroll
        for (int ni = 0; ni < 8; ni++)
            *(unsigned*)(scores + rowoff + jc + colbase + ni * 8) = p[ni];
        // packed max tree over this thread's 16 cols, then across tig quad
        __nv_bfloat162 m = *(__nv_bfloat162*)&p[0];
#pragma unroll
        for (int ni = 1; ni < 8; ni++) m = __hmax2(m, *(__nv_bfloat162*)&p[ni]);
        unsigned mu = *(unsigned*)&m;
        unsigned o1 = __shfl_xor_sync(0xFFFFFFFFu, mu, 1);
        m = __hmax2(m, *(__nv_bfloat162*)&o1);
        mu = *(unsigned*)&m;
        unsigned o2 = __shfl_xor_sync(0xFFFFFFFFu, mu, 2);
        m = __hmax2(m, *(__nv_bfloat162*)&o2);
        if (tig == 0) {
            __nv_bfloat16 ms = __hmax(m.x, m.y);
            bmax[(size_t)(t0 + row_l) * BMAXP + (jc >> 6) + wn] = ms;
        }
    }
}

// ---------------- K2: block select + candidate prune + exact top-4 --------
// one warp per token
__global__ void __launch_bounds__(128)
select_k(const __nv_bfloat16* __restrict__ bmax, const __nv_bfloat16* __restrict__ scores,
         const float* __restrict__ zi, const float* __restrict__ zc)
{
    __shared__ int scand[4][NCAND];
    const int wl = threadIdx.x >> 5;
    const int t = (blockIdx.x * blockDim.x + threadIdx.x) >> 5;
    const int lane = threadIdx.x & 31;
    if (t >= NTOK) return;

    // Phase A: lane-local top-8 of 786 blockmaxes
    float lv[8]; int lb[8];
#pragma unroll
    for (int k = 0; k < 8; k++) { lv[k] = -FLT_MAX; lb[k] = INT_MAX; }
    const __nv_bfloat16* bm = bmax + (size_t)t * BMAXP;
#pragma unroll
    for (int k = 0; k < 25; k++) {
        int b = lane + 32 * k;
        if (b < NBLK) {
            float v = __bfloat162float(bm[b]);
            if (v >= lv[7]) insK<8>(v, b, lv, lb);
        }
    }
    // extract top-16 blocks (warp-wide argmax, owner pops)
    int blk[16];
#pragma unroll
    for (int r = 0; r < 16; r++) {
        float cv = lv[0]; int cb = lb[0];
#pragma unroll
        for (int off = 16; off > 0; off >>= 1) {
            float ov = __shfl_xor_sync(0xFFFFFFFFu, cv, off);
            int   ob = __shfl_xor_sync(0xFFFFFFFFu, cb, off);
            if (better(ov, ob, cv, cb)) { cv = ov; cb = ob; }
        }
        blk[r] = cb;
        if (lb[0] == cb) {
#pragma unroll
            for (int k = 0; k < 7; k++) { lv[k] = lv[k+1]; lb[k] = lb[k+1]; }
            lv[7] = -FLT_MAX; lb[7] = INT_MAX;
        }
    }

    // Phase B: lane-local top-12 over the 16 blocks' 1024 bf16 scores
    float cv12[12]; int ci12[12];
#pragma unroll
    for (int k = 0; k < 12; k++) { cv12[k] = -FLT_MAX; ci12[k] = INT_MAX; }
    const __nv_bfloat16* srow = scores + (size_t)t * VOCP;
#pragma unroll
    for (int r = 0; r < 16; r++) {
        int j0 = blk[r] * 64 + lane * 2;
        unsigned u = *(const unsigned*)(srow + j0);
        __nv_bfloat162 b2 = *(__nv_bfloat162*)&u;
        float f0 = __bfloat162float(b2.x);
        float f1 = __bfloat162float(b2.y);
        if (f0 >= cv12[11]) insK<12>(f0, j0,     cv12, ci12);
        if (f1 >= cv12[11]) insK<12>(f1, j0 + 1, cv12, ci12);
    }
    // Phase C: extract top-24 candidates into smem
#pragma unroll
    for (int r = 0; r < NCAND; r++) {
        float cv = cv12[0]; int cb = ci12[0];
#pragma unroll
        for (int off = 16; off > 0; off >>= 1) {
            float ov = __shfl_xor_sync(0xFFFFFFFFu, cv, off);
            int   ob = __shfl_xor_sync(0xFFFFFFFFu, cb, off);
            if (better(ov, ob, cv, cb)) { cv = ov; cb = ob; }
        }
        if (lane == 0) scand[wl][r] = cb;
        if (ci12[0] == cb) {
#pragma unroll
            for (int k = 0; k < 11; k++) { cv12[k] = cv12[k+1]; ci12[k] = ci12[k+1]; }
            cv12[11] = -FLT_MAX; ci12[11] = INT_MAX;
        }
    }
    __syncwarp();

    // Phase D: exact fp32 rescore of 24 candidates -> top-4 + histogram
    const float* zr = zi + (size_t)t * LDIM;
    float a[8];
#pragma unroll
    for (int i = 0; i < 8; i++) a[i] = zr[lane + 32 * i];
    float tv[4] = {-FLT_MAX, -FLT_MAX, -FLT_MAX, -FLT_MAX};
    int   ti[4] = {INT_MAX, INT_MAX, INT_MAX, INT_MAX};
    for (int c = 0; c < NCAND; c += 2) {
        int j0c = scand[wl][c], j1c = scand[wl][c + 1];
        const float* b0 = zc + (size_t)j0c * LDIM;
        const float* b1 = zc + (size_t)j1c * LDIM;
        float s0 = 0.f, s1 = 0.f;
#pragma unroll
        for (int i = 0; i < 8; i++) {
            s0 += a[i] * b0[lane + 32 * i];
            s1 += a[i] * b1[lane + 32 * i];
        }
#pragma unroll
        for (int off = 16; off > 0; off >>= 1) {
            s0 += __shfl_xor_sync(0xFFFFFFFFu, s0, off);
            s1 += __shfl_xor_sync(0xFFFFFFFFu, s1, off);
        }
        insK<4>(s0, j0c, tv, ti);
        insK<4>(s1, j1c, tv, ti);
    }
    if (lane == 0) {
#pragma unroll
        for (int k = 0; k < 4; k++) {
            g_idx[t * 4 + k] = ti[k];
            atomicAdd(&g_counts[ti[k]], 1);
        }
    }
}

// ---------------- quantize -------------------------------------------------
__global__ void quant_k(const float* __restrict__ x, const float* __restrict__ cb,
                        float* __restrict__ out)
{
    int w = (blockIdx.x * blockDim.x + threadIdx.x) >> 5;   // token
    int lane = threadIdx.x & 31;
    if (w >= NTOK) return;
    const float* c0 = cb + (size_t)g_idx[w * 4 + 0] * DDIM;
    const float* c1 = cb + (size_t)g_idx[w * 4 + 1] * DDIM;
    const float* c2 = cb + (size_t)g_idx[w * 4 + 2] * DDIM;
    const float* c3 = cb + (size_t)g_idx[w * 4 + 3] * DDIM;
    double s = 0.0;
    for (int c = lane; c < DDIM; c += 32) {
        float qv = (((c0[c] + c1[c]) + c2[c]) + c3[c]) * 0.25f;
        float xv = x[(size_t)w * DDIM + c];
        float d = qv - xv;
        out[(size_t)w * DDIM + c] = xv + d;     // x + (q - x), matches STE
        g_q[(size_t)w * DDIM + c] = qv;
        s += (double)d * (double)d;
    }
#pragma unroll
    for (int off = 16; off > 0; off >>= 1)
        s += __shfl_down_sync(0xFFFFFFFFu, s, off);
    if (lane == 0) atomicAdd(&g_mse1, s);
}

// ---------------- entropy / usage ------------------------------------------
__global__ void ent_k()
{
    int i0 = blockIdx.x * blockDim.x + threadIdx.x;
    double e = 0.0; int nz = 0;
    for (int i = i0; i < VOC; i += gridDim.x * blockDim.x) {
        int c = g_counts[i];
        if (c > 0) {
            float p = (float)c * (1.0f / (NTOK * KSEL));
            e += (double)(p * logf(p + 1e-10f));
            nz++;
        }
    }
#pragma unroll
    for (int off = 16; off > 0; off >>= 1) {
        e  += __shfl_down_sync(0xFFFFFFFFu, e, off);
        nz += __shfl_down_sync(0xFFFFFFFFu, nz, off);
    }
    if ((threadIdx.x & 31) == 0) { atomicAdd(&g_ent, e); atomicAdd(&g_nz, nz); }
}

// ---------------- finalize scalars -----------------------------------------
__global__ void fin_k(float* __restrict__ out3)
{
    float lp = (float)(-g_ent);
    float mse1 = (float)(g_mse1 / ((double)NTOK * DDIM));
    float mse2 = (float)(g_mse2 / ((double)NTOK * LDIM));
    float loss = 1.25f * mse1 + 1.25f * mse2 + 0.1f * lp;
    out3[0] = loss;
    out3[1] = expf(lp);
    out3[2] = (float)g_nz / (float)VOC / (float)KSEL;
}

// ---------------- launch ----------------------------------------------------
static float* sym_f(const void* s) { void* p = nullptr; cudaGetSymbolAddress(&p, s); return (float*)p; }
static __nv_bfloat16* sym_b(const void* s) { void* p = nullptr; cudaGetSymbolAddress(&p, s); return (__nv_bfloat16*)p; }

extern "C" void kernel_launch(void* const* d_in, const int* in_sizes, int n_in,
                              void* d_out, int out_size)
{
    const float* x  = (const float*)d_in[0];
    const float* cb = (const float*)d_in[1];
    const float* Wi = (const float*)d_in[2];
    const float* bi = (const float*)d_in[3];
    const float* Wc = (const float*)d_in[4];
    const float* bc = (const float*)d_in[5];
    float* out = (float*)d_out;

    float* zi_pre = sym_f(g_zi_pre);
    float* zi     = sym_f(g_zi);
    float* zc     = sym_f(g_zc);
    float* q      = sym_f(g_q);
    __nv_bfloat16* zih = sym_b(g_zih);
    __nv_bfloat16* zch = sym_b(g_zch);
    __nv_bfloat16* scores = sym_b(g_scores);
    __nv_bfloat16* bmax   = sym_b(g_bmax);

    init_k<<<64, 256>>>();
    // zi_pre = x @ W_in + b_in ; zi = l2n(zi_pre) (+ bf16 copy)
    gemm_k<0><<<dim3(NTOK / 64, LDIM / 64), 256>>>(x, Wi, bi, zi_pre, nullptr, NTOK);
    norm_k<<<NTOK / 8, 256>>>(zi_pre, zi, zih, NTOK);
    // zc = l2n(codebook @ W_code + b_code) (+ bf16 copy)
    gemm_k<0><<<dim3((VOC + 63) / 64, LDIM / 64), 256>>>(cb, Wc, bc, zc, nullptr, VOC);
    norm_k<<<(VOC + 7) / 8, 256>>>(zc, zc, zch, VOC);
    // K1: bf16 MMA scores -> gmem + blockmax
    score_mma<<<dim3(NTOK / 128, VOCP / 128), 256>>>(zih, zch, scores, bmax);
    // K2: block-select + prune + exact top-4 + histogram
    select_k<<<NTOK / 4, 128>>>(bmax, scores, zi, zc);
    // quantize + STE output + mse1
    quant_k<<<NTOK / 8, 256>>>(x, cb, out);
    // mse2 = sum((q @ W_code + b_code - zi_pre)^2)
    gemm_k<1><<<dim3(NTOK / 64, LDIM / 64), 256>>>(q, Wc, bc, nullptr, zi_pre, NTOK);
    ent_k<<<64, 256>>>();
    fin_k<<<1, 1>>>(out + (size_t)NTOK * DDIM);
}

// round 9
// speedup vs baseline: 4.5125x; 1.0705x over previous
#include <cuda_runtime.h>
#include <cuda_bf16.h>
#include <math.h>
#include <float.h>
#include <limits.h>
#include <stdint.h>

// Problem constants
#define NTOK 4096      // B*S
#define DDIM 768
#define LDIM 256
#define VOC  50265
#define VOCP 50304     // 393 tiles of 128
#define NBLK 786       // 64-code blocks (VOCP/64)
#define BMAXP 788      // padded row
#define KSEL 4
#define NCAND 24

// ---------------- scratch (device globals; no allocations) ----------------
__device__ float  g_zi_pre[NTOK * LDIM];      // x@W_in+b (kept for mse2 ref)
__device__ float  g_zi[NTOK * LDIM];          // normalized
__device__ float  g_zc[VOC * LDIM];           // normalized latent codebook
__device__ float  g_zcn[VOC];                 // reciprocal norm: zc_pre = zc * g_zcn
__device__ __nv_bfloat16 g_zih[NTOK * LDIM];
__device__ __nv_bfloat16 g_zch[VOC * LDIM];
__device__ __nv_bfloat16 g_scores[(size_t)NTOK * VOCP];   // all approx scores
__device__ __nv_bfloat16 g_bmax[(size_t)NTOK * BMAXP];    // per-64-block max
__device__ int    g_idx[NTOK * KSEL];
__device__ int    g_counts[VOC];
__device__ double g_mse1, g_mse2, g_ent;
__device__ int    g_nz;

// ---------------- helpers ----------------
__device__ __forceinline__ uint32_t smem_u32(const void* p) {
    uint32_t a;
    asm("{ .reg .u64 t; cvta.to.shared.u64 t, %1; cvt.u32.u64 %0, t; }" : "=r"(a) : "l"(p));
    return a;
}
__device__ __forceinline__ bool better(float v, int j, float v2, int j2) {
    return (v > v2) || (v == v2 && j < j2);
}
template <int K>
__device__ __forceinline__ void insK(float v, int j, float tv[K], int ti[K]) {
    if (!better(v, j, tv[K-1], ti[K-1])) return;
    tv[K-1] = v; ti[K-1] = j;
#pragma unroll
    for (int k = K-1; k > 0; k--) {
        if (better(tv[k], ti[k], tv[k-1], ti[k-1])) {
            float fv = tv[k]; tv[k] = tv[k-1]; tv[k-1] = fv;
            int   fi = ti[k]; ti[k] = ti[k-1]; ti[k-1] = fi;
        }
    }
}

// ---------------- bf16 mma + ldmatrix helpers ----------------
__device__ __forceinline__ void mma_bf16(float d[4], const unsigned a[4], const unsigned b[2]) {
    asm("mma.sync.aligned.m16n8k16.row.col.f32.bf16.bf16.f32 "
        "{%0,%1,%2,%3},{%4,%5,%6,%7},{%8,%9},{%0,%1,%2,%3};"
        : "+f"(d[0]), "+f"(d[1]), "+f"(d[2]), "+f"(d[3])
        : "r"(a[0]), "r"(a[1]), "r"(a[2]), "r"(a[3]), "r"(b[0]), "r"(b[1]));
}
__device__ __forceinline__ void ldsm_x4(uint32_t addr, unsigned r[4]) {
    asm volatile("ldmatrix.sync.aligned.m8n8.x4.shared.b16 {%0,%1,%2,%3}, [%4];"
        : "=r"(r[0]), "=r"(r[1]), "=r"(r[2]), "=r"(r[3]) : "r"(addr));
}

// ---------------- init ----------------
__global__ void init_k() {
    int i = blockIdx.x * blockDim.x + threadIdx.x;
    for (int v = i; v < VOC; v += gridDim.x * blockDim.x) g_counts[v] = 0;
    if (i == 0) { g_mse1 = 0.0; g_mse2 = 0.0; g_ent = 0.0; g_nz = 0; }
}

// ---------------- GEMM (R1 proven): C[M,256] = A[M,768] @ W + bias --------
__global__ void __launch_bounds__(256, 2)
gemm_k(const float* __restrict__ A, const float* __restrict__ W,
       const float* __restrict__ bias, float* __restrict__ C, int M)
{
    __shared__ float As[32][68];   // k-major: As[k][m]
    __shared__ float Ws[32][68];   // Ws[k][n]
    const int tid = threadIdx.x;
    const int m0 = blockIdx.x * 64, n0 = blockIdx.y * 64;
    const int tx = tid & 15, ty = tid >> 4;

    float acc[4][4] = {};
    for (int c0 = 0; c0 < DDIM; c0 += 32) {
#pragma unroll
        for (int t = 0; t < 2; t++) {            // A tile -> transposed store
            int li = tid * 2 + t;
            int row = li >> 3, kq = li & 7;
            float4 v = make_float4(0.f, 0.f, 0.f, 0.f);
            if (m0 + row < M)
                v = *(const float4*)&A[(size_t)(m0 + row) * DDIM + c0 + kq * 4];
            As[kq*4+0][row] = v.x; As[kq*4+1][row] = v.y;
            As[kq*4+2][row] = v.z; As[kq*4+3][row] = v.w;
        }
#pragma unroll
        for (int t = 0; t < 2; t++) {            // W tile -> direct store
            int li = tid * 2 + t;
            int r = li >> 4, nq = li & 15;
            float4 v = *(const float4*)&W[(size_t)(c0 + r) * LDIM + n0 + nq * 4];
            *(float4*)&Ws[r][nq * 4] = v;
        }
        __syncthreads();
#pragma unroll
        for (int kk = 0; kk < 32; kk++) {
            float4 a4 = *(float4*)&As[kk][ty * 4];
            float4 b4 = *(float4*)&Ws[kk][tx * 4];
            float av[4] = {a4.x, a4.y, a4.z, a4.w};
            float bv[4] = {b4.x, b4.y, b4.z, b4.w};
#pragma unroll
            for (int i = 0; i < 4; i++)
#pragma unroll
                for (int j = 0; j < 4; j++)
                    acc[i][j] += av[i] * bv[j];
        }
        __syncthreads();
    }
#pragma unroll
    for (int i = 0; i < 4; i++) {
        int row = m0 + ty * 4 + i;
        if (row < M) {
#pragma unroll
            for (int j = 0; j < 4; j++) {
                int col = n0 + tx * 4 + j;
                C[(size_t)row * LDIM + col] = acc[i][j] + bias[col];
            }
        }
    }
}

// ---------------- row L2-normalize, fused bf16 emit (+ optional recip) -----
__global__ void norm_k(const float* __restrict__ in, float* __restrict__ out,
                       __nv_bfloat16* __restrict__ outh, float* __restrict__ rnorm, int M)
{
    int w = (blockIdx.x * blockDim.x + threadIdx.x) >> 5;
    int lane = threadIdx.x & 31;
    if (w >= M) return;
    const float* r = in + (size_t)w * LDIM;
    float vals[8];
    float s = 0.f;
#pragma unroll
    for (int i = 0; i < 8; i++) { vals[i] = r[lane + 32 * i]; s += vals[i] * vals[i]; }
#pragma unroll
    for (int off = 16; off > 0; off >>= 1)
        s += __shfl_xor_sync(0xFFFFFFFFu, s, off);
    float t = s + 1e-12f;
    float sc = rsqrtf(t);
    sc = sc * (1.5f - 0.5f * t * sc * sc);   // Newton: ~1 ulp
    float* o = out + (size_t)w * LDIM;
    __nv_bfloat16* oh = outh + (size_t)w * LDIM;
#pragma unroll
    for (int i = 0; i < 8; i++) {
        float v = vals[i] * sc;
        o[lane + 32 * i] = v;
        oh[lane + 32 * i] = __float2bfloat16(v);
    }
    if (rnorm && lane == 0) rnorm[w] = 1.0f / sc;
}

// ---------------- K1: MMA scores -> bf16 store + 64-block max --------------
// grid (NTOK/128, VOCP/128). ldmatrix fragment loads; no score scan.
__global__ void __launch_bounds__(256, 2)
score_mma(const __nv_bfloat16* __restrict__ zih, const __nv_bfloat16* __restrict__ zch,
          __nv_bfloat16* __restrict__ scores, __nv_bfloat16* __restrict__ bmax)
{
    __shared__ __align__(16) char smembuf[40960];
    const int tid = threadIdx.x;
    const int w = tid >> 5, lane = tid & 31;
    const int grp = lane >> 2, tig = lane & 3;
    const int wm = w >> 1, wn = w & 1;            // 4 x 2 warp grid
    const int t0 = blockIdx.x * 128;
    const int jc = blockIdx.y * 128;

    const int lrow = tid >> 1;                    // loader row 0..127
    const int eo   = (tid & 1) * 16;

    char* bufA0 = smembuf;
    char* bufA1 = smembuf + 10240;
    char* bufB0 = smembuf + 20480;
    char* bufB1 = smembuf + 30720;
    const uint32_t sm0 = smem_u32(smembuf);

    // ldmatrix per-thread offsets (80B pitch rows; conflict-free phases)
    uint32_t offA[2], offB[4];
    {
        int la = lane & 15, ha = lane >> 4;       // A: row sel, k half
#pragma unroll
        for (int mi = 0; mi < 2; mi++)
            offA[mi] = (uint32_t)((wm * 32 + mi * 16 + la) * 80 + ha * 16);
        int rb = ((lane >> 4) & 1) * 8 + (lane & 7);
        int cbb = ((lane >> 3) & 1) * 16;
#pragma unroll
        for (int p = 0; p < 4; p++)
            offB[p] = (uint32_t)((wn * 64 + p * 16 + rb) * 80 + cbb);
    }

    float acc[2][8][4] = {};
    int jrow = jc + lrow;
    bool bok = (jrow < VOC);
    const __nv_bfloat16* arow = zih + (size_t)(t0 + lrow) * LDIM + eo;
    const __nv_bfloat16* brow = zch + (size_t)jrow * LDIM + eo;

    // prologue: stage 0
    {
        uint4 a0 = *(const uint4*)(arow);
        uint4 a1 = *(const uint4*)(arow + 8);
        uint4 b0 = {0,0,0,0}, b1 = {0,0,0,0};
        if (bok) { b0 = *(const uint4*)(brow); b1 = *(const uint4*)(brow + 8); }
        char* da = bufA0 + lrow * 80 + eo * 2;
        char* db = bufB0 + lrow * 80 + eo * 2;
        *(uint4*)da = a0; *(uint4*)(da + 16) = a1;
        *(uint4*)db = b0; *(uint4*)(db + 16) = b1;
    }

#pragma unroll
    for (int s = 0; s < 8; s++) {            // 8 stages of 32 k-dims
        __syncthreads();
        uint4 na0, na1, nb0, nb1;
        bool pf = (s < 7);
        if (pf) {
            int ko = (s + 1) * 32;
            na0 = *(const uint4*)(arow + ko);
            na1 = *(const uint4*)(arow + ko + 8);
            uint4 z = {0,0,0,0}; nb0 = z; nb1 = z;
            if (bok) {
                nb0 = *(const uint4*)(brow + ko);
                nb1 = *(const uint4*)(brow + ko + 8);
            }
        }
        const uint32_t sA = sm0 + (uint32_t)(((s & 1) ? bufA1 : bufA0) - smembuf);
        const uint32_t sB = sm0 + (uint32_t)(((s & 1) ? bufB1 : bufB0) - smembuf);
#pragma unroll
        for (int ks = 0; ks < 2; ks++) {
            unsigned a0[4], a1[4];
            ldsm_x4(sA + offA[0] + ks * 32, a0);
            ldsm_x4(sA + offA[1] + ks * 32, a1);
#pragma unroll
            for (int p = 0; p < 4; p++) {
                unsigned bb[4];
                ldsm_x4(sB + offB[p] + ks * 32, bb);
                mma_bf16(acc[0][2*p],     a0, bb);
                mma_bf16(acc[0][2*p + 1], a0, bb + 2);
                mma_bf16(acc[1][2*p],     a1, bb);
                mma_bf16(acc[1][2*p + 1], a1, bb + 2);
            }
        }
        if (pf) {
            char* da = ((s & 1) ? bufA0 : bufA1) + lrow * 80 + eo * 2;
            char* db = ((s & 1) ? bufB0 : bufB1) + lrow * 80 + eo * 2;
            *(uint4*)da = na0; *(uint4*)(da + 16) = na1;
            *(uint4*)db = nb0; *(uint4*)(db + 16) = nb1;
        }
    }

    // ---- epilogue: cvt bf16, store, packed block-max (no syncs needed) ----
    const int colbase = wn * 64 + tig * 2;
#pragma unroll
    for (int mi = 0; mi < 2; mi++)
#pragma unroll
    for (int h = 0; h < 2; h++) {
        int row_l = wm * 32 + mi * 16 + grp + h * 8;
        size_t rowoff = (size_t)(t0 + row_l) * VOCP;
        unsigned p[8];
#pragma unroll
        for (int ni = 0; ni < 8; ni++) {
            float2 f2 = make_float2(acc[mi][ni][2*h], acc[mi][ni][2*h + 1]);
            __nv_bfloat162 bb = __float22bfloat162_rn(f2);   // .x -> low half
            p[ni] = *(unsigned*)&bb;
        }
        if (jc + 128 > VOC) {        // mask tail columns with bf16 -inf
#pragma unroll
            for (int ni = 0; ni < 8; ni++) {
                int j = jc + colbase + ni * 8;
                if (j >= VOC)     p[ni] = (p[ni] & 0xFFFF0000u) | 0x0000FF80u;
                if (j + 1 >= VOC) p[ni] = (p[ni] & 0x0000FFFFu) | 0xFF800000u;
            }
        }
#pragma unroll
        for (int ni = 0; ni < 8; ni++)
            *(unsigned*)(scores + rowoff + jc + colbase + ni * 8) = p[ni];
        // packed max tree over this thread's 16 cols, then across tig quad
        __nv_bfloat162 m = *(__nv_bfloat162*)&p[0];
#pragma unroll
        for (int ni = 1; ni < 8; ni++) m = __hmax2(m, *(__nv_bfloat162*)&p[ni]);
        unsigned mu = *(unsigned*)&m;
        unsigned o1 = __shfl_xor_sync(0xFFFFFFFFu, mu, 1);
        m = __hmax2(m, *(__nv_bfloat162*)&o1);
        mu = *(unsigned*)&m;
        unsigned o2 = __shfl_xor_sync(0xFFFFFFFFu, mu, 2);
        m = __hmax2(m, *(__nv_bfloat162*)&o2);
        if (tig == 0) {
            __nv_bfloat16 ms = __hmax(m.x, m.y);
            bmax[(size_t)(t0 + row_l) * BMAXP + (jc >> 6) + wn] = ms;
        }
    }
}

// ---------------- K2: block select + candidate prune + exact top-4 --------
// one warp per token
__global__ void __launch_bounds__(128)
select_k(const __nv_bfloat16* __restrict__ bmax, const __nv_bfloat16* __restrict__ scores,
         const float* __restrict__ zi, const float* __restrict__ zc)
{
    __shared__ int scand[4][NCAND];
    const int wl = threadIdx.x >> 5;
    const int t = (blockIdx.x * blockDim.x + threadIdx.x) >> 5;
    const int lane = threadIdx.x & 31;
    if (t >= NTOK) return;

    // Phase A: lane-local top-8 of 786 blockmaxes
    float lv[8]; int lb[8];
#pragma unroll
    for (int k = 0; k < 8; k++) { lv[k] = -FLT_MAX; lb[k] = INT_MAX; }
    const __nv_bfloat16* bm = bmax + (size_t)t * BMAXP;
#pragma unroll
    for (int k = 0; k < 25; k++) {
        int b = lane + 32 * k;
        if (b < NBLK) {
            float v = __bfloat162float(bm[b]);
            if (v >= lv[7]) insK<8>(v, b, lv, lb);
        }
    }
    // extract top-16 blocks (warp-wide argmax, owner pops)
    int blk[16];
#pragma unroll
    for (int r = 0; r < 16; r++) {
        float cv = lv[0]; int cb = lb[0];
#pragma unroll
        for (int off = 16; off > 0; off >>= 1) {
            float ov = __shfl_xor_sync(0xFFFFFFFFu, cv, off);
            int   ob = __shfl_xor_sync(0xFFFFFFFFu, cb, off);
            if (better(ov, ob, cv, cb)) { cv = ov; cb = ob; }
        }
        blk[r] = cb;
        if (lb[0] == cb) {
#pragma unroll
            for (int k = 0; k < 7; k++) { lv[k] = lv[k+1]; lb[k] = lb[k+1]; }
            lv[7] = -FLT_MAX; lb[7] = INT_MAX;
        }
    }

    // Phase B: lane-local top-12 over the 16 blocks' 1024 bf16 scores
    float cv12[12]; int ci12[12];
#pragma unroll
    for (int k = 0; k < 12; k++) { cv12[k] = -FLT_MAX; ci12[k] = INT_MAX; }
    const __nv_bfloat16* srow = scores + (size_t)t * VOCP;
#pragma unroll
    for (int r = 0; r < 16; r++) {
        int j0 = blk[r] * 64 + lane * 2;
        unsigned u = *(const unsigned*)(srow + j0);
        __nv_bfloat162 b2 = *(__nv_bfloat162*)&u;
        float f0 = __bfloat162float(b2.x);
        float f1 = __bfloat162float(b2.y);
        if (f0 >= cv12[11]) insK<12>(f0, j0,     cv12, ci12);
        if (f1 >= cv12[11]) insK<12>(f1, j0 + 1, cv12, ci12);
    }
    // Phase C: extract top-24 candidates into smem
#pragma unroll
    for (int r = 0; r < NCAND; r++) {
        float cv = cv12[0]; int cb = ci12[0];
#pragma unroll
        for (int off = 16; off > 0; off >>= 1) {
            float ov = __shfl_xor_sync(0xFFFFFFFFu, cv, off);
            int   ob = __shfl_xor_sync(0xFFFFFFFFu, cb, off);
            if (better(ov, ob, cv, cb)) { cv = ov; cb = ob; }
        }
        if (lane == 0) scand[wl][r] = cb;
        if (ci12[0] == cb) {
#pragma unroll
            for (int k = 0; k < 11; k++) { cv12[k] = cv12[k+1]; ci12[k] = ci12[k+1]; }
            cv12[11] = -FLT_MAX; ci12[11] = INT_MAX;
        }
    }
    __syncwarp();

    // Phase D: exact fp32 rescore of 24 candidates -> top-4 + histogram
    const float* zr = zi + (size_t)t * LDIM;
    float a[8];
#pragma unroll
    for (int i = 0; i < 8; i++) a[i] = zr[lane + 32 * i];
    float tv[4] = {-FLT_MAX, -FLT_MAX, -FLT_MAX, -FLT_MAX};
    int   ti[4] = {INT_MAX, INT_MAX, INT_MAX, INT_MAX};
    for (int c = 0; c < NCAND; c += 2) {
        int j0c = scand[wl][c], j1c = scand[wl][c + 1];
        const float* b0 = zc + (size_t)j0c * LDIM;
        const float* b1 = zc + (size_t)j1c * LDIM;
        float s0 = 0.f, s1 = 0.f;
#pragma unroll
        for (int i = 0; i < 8; i++) {
            s0 += a[i] * b0[lane + 32 * i];
            s1 += a[i] * b1[lane + 32 * i];
        }
#pragma unroll
        for (int off = 16; off > 0; off >>= 1) {
            s0 += __shfl_xor_sync(0xFFFFFFFFu, s0, off);
            s1 += __shfl_xor_sync(0xFFFFFFFFu, s1, off);
        }
        insK<4>(s0, j0c, tv, ti);
        insK<4>(s1, j1c, tv, ti);
    }
    if (lane == 0) {
#pragma unroll
        for (int k = 0; k < 4; k++) {
            g_idx[t * 4 + k] = ti[k];
            atomicAdd(&g_counts[ti[k]], 1);
        }
    }
}

// ---------------- quantize + STE out + mse1 --------------------------------
__global__ void quant_k(const float* __restrict__ x, const float* __restrict__ cb,
                        float* __restrict__ out)
{
    int w = (blockIdx.x * blockDim.x + threadIdx.x) >> 5;   // token
    int lane = threadIdx.x & 31;
    if (w >= NTOK) return;
    const float* c0 = cb + (size_t)g_idx[w * 4 + 0] * DDIM;
    const float* c1 = cb + (size_t)g_idx[w * 4 + 1] * DDIM;
    const float* c2 = cb + (size_t)g_idx[w * 4 + 2] * DDIM;
    const float* c3 = cb + (size_t)g_idx[w * 4 + 3] * DDIM;
    double s = 0.0;
    for (int c = lane; c < DDIM; c += 32) {
        float qv = (((c0[c] + c1[c]) + c2[c]) + c3[c]) * 0.25f;
        float xv = x[(size_t)w * DDIM + c];
        float d = qv - xv;
        out[(size_t)w * DDIM + c] = xv + d;     // x + (q - x), matches STE
        s += (double)d * (double)d;
    }
#pragma unroll
    for (int off = 16; off > 0; off >>= 1)
        s += __shfl_down_sync(0xFFFFFFFFu, s, off);
    if (lane == 0) atomicAdd(&g_mse1, s);
}

// ---------------- mse2 via zc reuse: q@Wc+b == mean_k zc_pre[j_k] ----------
__global__ void mse2_k(const float* __restrict__ zc, const float* __restrict__ rn,
                       const float* __restrict__ zi_pre)
{
    int t = (blockIdx.x * blockDim.x + threadIdx.x) >> 5;
    int lane = threadIdx.x & 31;
    if (t >= NTOK) return;
    int j0 = g_idx[t * 4 + 0], j1 = g_idx[t * 4 + 1];
    int j2 = g_idx[t * 4 + 2], j3 = g_idx[t * 4 + 3];
    float w0 = 0.25f * rn[j0], w1 = 0.25f * rn[j1];
    float w2 = 0.25f * rn[j2], w3 = 0.25f * rn[j3];
    const float* z0 = zc + (size_t)j0 * LDIM;
    const float* z1 = zc + (size_t)j1 * LDIM;
    const float* z2 = zc + (size_t)j2 * LDIM;
    const float* z3 = zc + (size_t)j3 * LDIM;
    const float* rp = zi_pre + (size_t)t * LDIM;
    double s = 0.0;
#pragma unroll
    for (int i = 0; i < 8; i++) {
        int c = lane + 32 * i;
        float v = z0[c] * w0 + z1[c] * w1 + z2[c] * w2 + z3[c] * w3 - rp[c];
        s += (double)v * (double)v;
    }
#pragma unroll
    for (int off = 16; off > 0; off >>= 1)
        s += __shfl_down_sync(0xFFFFFFFFu, s, off);
    if (lane == 0) atomicAdd(&g_mse2, s);
}

// ---------------- entropy / usage ------------------------------------------
__global__ void ent_k()
{
    int i0 = blockIdx.x * blockDim.x + threadIdx.x;
    double e = 0.0; int nz = 0;
    for (int i = i0; i < VOC; i += gridDim.x * blockDim.x) {
        int c = g_counts[i];
        if (c > 0) {
            float p = (float)c * (1.0f / (NTOK * KSEL));
            e += (double)(p * logf(p + 1e-10f));
            nz++;
        }
    }
#pragma unroll
    for (int off = 16; off > 0; off >>= 1) {
        e  += __shfl_down_sync(0xFFFFFFFFu, e, off);
        nz += __shfl_down_sync(0xFFFFFFFFu, nz, off);
    }
    if ((threadIdx.x & 31) == 0) { atomicAdd(&g_ent, e); atomicAdd(&g_nz, nz); }
}

// ---------------- finalize scalars -----------------------------------------
__global__ void fin_k(float* __restrict__ out3)
{
    float lp = (float)(-g_ent);
    float mse1 = (float)(g_mse1 / ((double)NTOK * DDIM));
    float mse2 = (float)(g_mse2 / ((double)NTOK * LDIM));
    float loss = 1.25f * mse1 + 1.25f * mse2 + 0.1f * lp;
    out3[0] = loss;
    out3[1] = expf(lp);
    out3[2] = (float)g_nz / (float)VOC / (float)KSEL;
}

// ---------------- launch ----------------------------------------------------
static float* sym_f(const void* s) { void* p = nullptr; cudaGetSymbolAddress(&p, s); return (float*)p; }
static __nv_bfloat16* sym_b(const void* s) { void* p = nullptr; cudaGetSymbolAddress(&p, s); return (__nv_bfloat16*)p; }

extern "C" void kernel_launch(void* const* d_in, const int* in_sizes, int n_in,
                              void* d_out, int out_size)
{
    const float* x  = (const float*)d_in[0];
    const float* cb = (const float*)d_in[1];
    const float* Wi = (const float*)d_in[2];
    const float* bi = (const float*)d_in[3];
    const float* Wc = (const float*)d_in[4];
    const float* bc = (const float*)d_in[5];
    float* out = (float*)d_out;

    float* zi_pre = sym_f(g_zi_pre);
    float* zi     = sym_f(g_zi);
    float* zc     = sym_f(g_zc);
    float* zcn    = sym_f(g_zcn);
    __nv_bfloat16* zih = sym_b(g_zih);
    __nv_bfloat16* zch = sym_b(g_zch);
    __nv_bfloat16* scores = sym_b(g_scores);
    __nv_bfloat16* bmax   = sym_b(g_bmax);

    init_k<<<64, 256>>>();
    // zi_pre = x @ W_in + b_in ; zi = l2n(zi_pre) (+ bf16 copy)
    gemm_k<<<dim3(NTOK / 64, LDIM / 64), 256>>>(x, Wi, bi, zi_pre, NTOK);
    norm_k<<<NTOK / 8, 256>>>(zi_pre, zi, zih, nullptr, NTOK);
    // zc = l2n(codebook @ W_code + b_code) (+ bf16 copy + recip norm)
    gemm_k<<<dim3((VOC + 63) / 64, LDIM / 64), 256>>>(cb, Wc, bc, zc, VOC);
    norm_k<<<(VOC + 7) / 8, 256>>>(zc, zc, zch, zcn, VOC);
    // K1: bf16 MMA scores (ldmatrix) -> gmem + blockmax
    score_mma<<<dim3(NTOK / 128, VOCP / 128), 256>>>(zih, zch, scores, bmax);
    // K2: block-select + prune + exact top-4 + histogram
    select_k<<<NTOK / 4, 128>>>(bmax, scores, zi, zc);
    // quantize + STE output + mse1
    quant_k<<<NTOK / 8, 256>>>(x, cb, out);
    // mse2 without a GEMM: q@Wc+b == mean of selected zc_pre rows
    mse2_k<<<NTOK / 8, 256>>>(zc, zcn, zi_pre);
    ent_k<<<64, 256>>>();
    fin_k<<<1, 1>>>(out + (size_t)NTOK * DDIM);
}

// round 10
// speedup vs baseline: 4.8510x; 1.0750x over previous
#include <cuda_runtime.h>
#include <cuda_bf16.h>
#include <math.h>
#include <float.h>
#include <limits.h>
#include <stdint.h>

// Problem constants
#define NTOK 4096      // B*S
#define DDIM 768
#define LDIM 256
#define VOC  50265
#define VOCP 50304     // 393 tiles of 128
#define NBLK 786       // 64-code blocks (VOCP/64)
#define BMAXP 788      // padded row
#define KSEL 4
#define NCAND 24

// ---------------- scratch (device globals; no allocations) ----------------
__device__ float  g_zi_pre[NTOK * LDIM];      // x@W_in+b (kept for mse2 ref)
__device__ float  g_zi[NTOK * LDIM];          // normalized
__device__ float  g_zc[VOC * LDIM];           // normalized latent codebook
__device__ float  g_zcn[VOC];                 // reciprocal norm: zc_pre = zc * g_zcn
__device__ __nv_bfloat16 g_zih[NTOK * LDIM];
__device__ __nv_bfloat16 g_zch[VOC * LDIM];
__device__ __nv_bfloat16 g_scores[(size_t)NTOK * VOCP];   // all approx scores
__device__ __nv_bfloat16 g_bmax[(size_t)NTOK * BMAXP];    // per-64-block max
__device__ int    g_idx[NTOK * KSEL];
__device__ int    g_counts[VOC];
__device__ double g_mse1, g_mse2, g_ent;
__device__ int    g_nz;

// ---------------- helpers ----------------
__device__ __forceinline__ uint32_t smem_u32(const void* p) {
    uint32_t a;
    asm("{ .reg .u64 t; cvta.to.shared.u64 t, %1; cvt.u32.u64 %0, t; }" : "=r"(a) : "l"(p));
    return a;
}
__device__ __forceinline__ bool better(float v, int j, float v2, int j2) {
    return (v > v2) || (v == v2 && j < j2);
}
template <int K>
__device__ __forceinline__ void insK(float v, int j, float tv[K], int ti[K]) {
    if (!better(v, j, tv[K-1], ti[K-1])) return;
    tv[K-1] = v; ti[K-1] = j;
#pragma unroll
    for (int k = K-1; k > 0; k--) {
        if (better(tv[k], ti[k], tv[k-1], ti[k-1])) {
            float fv = tv[k]; tv[k] = tv[k-1]; tv[k-1] = fv;
            int   fi = ti[k]; ti[k] = ti[k-1]; ti[k-1] = fi;
        }
    }
}

// ---------------- bf16 mma + ldmatrix + cp.async helpers ----------------
__device__ __forceinline__ void mma_bf16(float d[4], const unsigned a[4], const unsigned b[2]) {
    asm("mma.sync.aligned.m16n8k16.row.col.f32.bf16.bf16.f32 "
        "{%0,%1,%2,%3},{%4,%5,%6,%7},{%8,%9},{%0,%1,%2,%3};"
        : "+f"(d[0]), "+f"(d[1]), "+f"(d[2]), "+f"(d[3])
        : "r"(a[0]), "r"(a[1]), "r"(a[2]), "r"(a[3]), "r"(b[0]), "r"(b[1]));
}
__device__ __forceinline__ void ldsm_x4(uint32_t addr, unsigned r[4]) {
    asm volatile("ldmatrix.sync.aligned.m8n8.x4.shared.b16 {%0,%1,%2,%3}, [%4];"
        : "=r"(r[0]), "=r"(r[1]), "=r"(r[2]), "=r"(r[3]) : "r"(addr));
}
__device__ __forceinline__ void cp16(uint32_t dst, const void* src, int ssz) {
    asm volatile("cp.async.cg.shared.global [%0], [%1], 16, %2;"
        :: "r"(dst), "l"(src), "r"(ssz) : "memory");
}
#define CP_COMMIT() asm volatile("cp.async.commit_group;" ::: "memory")
#define CP_WAIT0()  asm volatile("cp.async.wait_group 0;" ::: "memory")

// ---------------- init ----------------
__global__ void init_k() {
    int i = blockIdx.x * blockDim.x + threadIdx.x;
    for (int v = i; v < VOC; v += gridDim.x * blockDim.x) g_counts[v] = 0;
    if (i == 0) { g_mse1 = 0.0; g_mse2 = 0.0; g_ent = 0.0; g_nz = 0; }
}

// ---------------- GEMM (R1 proven): C[M,256] = A[M,768] @ W + bias --------
__global__ void __launch_bounds__(256, 2)
gemm_k(const float* __restrict__ A, const float* __restrict__ W,
       const float* __restrict__ bias, float* __restrict__ C, int M)
{
    __shared__ float As[32][68];   // k-major: As[k][m]
    __shared__ float Ws[32][68];   // Ws[k][n]
    const int tid = threadIdx.x;
    const int m0 = blockIdx.x * 64, n0 = blockIdx.y * 64;
    const int tx = tid & 15, ty = tid >> 4;

    float acc[4][4] = {};
    for (int c0 = 0; c0 < DDIM; c0 += 32) {
#pragma unroll
        for (int t = 0; t < 2; t++) {            // A tile -> transposed store
            int li = tid * 2 + t;
            int row = li >> 3, kq = li & 7;
            float4 v = make_float4(0.f, 0.f, 0.f, 0.f);
            if (m0 + row < M)
                v = *(const float4*)&A[(size_t)(m0 + row) * DDIM + c0 + kq * 4];
            As[kq*4+0][row] = v.x; As[kq*4+1][row] = v.y;
            As[kq*4+2][row] = v.z; As[kq*4+3][row] = v.w;
        }
#pragma unroll
        for (int t = 0; t < 2; t++) {            // W tile -> direct store
            int li = tid * 2 + t;
            int r = li >> 4, nq = li & 15;
            float4 v = *(const float4*)&W[(size_t)(c0 + r) * LDIM + n0 + nq * 4];
            *(float4*)&Ws[r][nq * 4] = v;
        }
        __syncthreads();
#pragma unroll
        for (int kk = 0; kk < 32; kk++) {
            float4 a4 = *(float4*)&As[kk][ty * 4];
            float4 b4 = *(float4*)&Ws[kk][tx * 4];
            float av[4] = {a4.x, a4.y, a4.z, a4.w};
            float bv[4] = {b4.x, b4.y, b4.z, b4.w};
#pragma unroll
            for (int i = 0; i < 4; i++)
#pragma unroll
                for (int j = 0; j < 4; j++)
                    acc[i][j] += av[i] * bv[j];
        }
        __syncthreads();
    }
#pragma unroll
    for (int i = 0; i < 4; i++) {
        int row = m0 + ty * 4 + i;
        if (row < M) {
#pragma unroll
            for (int j = 0; j < 4; j++) {
                int col = n0 + tx * 4 + j;
                C[(size_t)row * LDIM + col] = acc[i][j] + bias[col];
            }
        }
    }
}

// ---------------- row L2-normalize, fused bf16 emit (+ optional recip) -----
__global__ void norm_k(const float* __restrict__ in, float* __restrict__ out,
                       __nv_bfloat16* __restrict__ outh, float* __restrict__ rnorm, int M)
{
    int w = (blockIdx.x * blockDim.x + threadIdx.x) >> 5;
    int lane = threadIdx.x & 31;
    if (w >= M) return;
    const float* r = in + (size_t)w * LDIM;
    float vals[8];
    float s = 0.f;
#pragma unroll
    for (int i = 0; i < 8; i++) { vals[i] = r[lane + 32 * i]; s += vals[i] * vals[i]; }
#pragma unroll
    for (int off = 16; off > 0; off >>= 1)
        s += __shfl_xor_sync(0xFFFFFFFFu, s, off);
    float t = s + 1e-12f;
    float sc = rsqrtf(t);
    sc = sc * (1.5f - 0.5f * t * sc * sc);   // Newton: ~1 ulp
    float* o = out + (size_t)w * LDIM;
    __nv_bfloat16* oh = outh + (size_t)w * LDIM;
#pragma unroll
    for (int i = 0; i < 8; i++) {
        float v = vals[i] * sc;
        o[lane + 32 * i] = v;
        oh[lane + 32 * i] = __float2bfloat16(v);
    }
    if (rnorm && lane == 0) rnorm[w] = 1.0f / sc;
}

// ---------------- K1: MMA scores -> bf16 store + 64-block max --------------
// grid (NTOK/128, VOCP/128). cp.async double-buffer; ldmatrix fragments.
__global__ void __launch_bounds__(256, 2)
score_mma(const __nv_bfloat16* __restrict__ zih, const __nv_bfloat16* __restrict__ zch,
          __nv_bfloat16* __restrict__ scores, __nv_bfloat16* __restrict__ bmax)
{
    __shared__ __align__(16) char smembuf[40960];
    const int tid = threadIdx.x;
    const int w = tid >> 5, lane = tid & 31;
    const int grp = lane >> 2, tig = lane & 3;
    const int wm = w >> 1, wn = w & 1;            // 4 x 2 warp grid
    const int t0 = blockIdx.x * 128;
    const int jc = blockIdx.y * 128;

    const int lrow = tid >> 1;                    // loader row 0..127
    const int eo   = (tid & 1) * 16;

    const uint32_t sm0 = smem_u32(smembuf);
    const uint32_t stA[2] = {sm0,         sm0 + 10240};
    const uint32_t stB[2] = {sm0 + 20480, sm0 + 30720};

    // ldmatrix per-thread offsets (80B pitch rows; conflict-free phases)
    uint32_t offA[2], offB[4];
    {
        int la = lane & 15, ha = lane >> 4;       // A: row sel, k half
#pragma unroll
        for (int mi = 0; mi < 2; mi++)
            offA[mi] = (uint32_t)((wm * 32 + mi * 16 + la) * 80 + ha * 16);
        int rb = ((lane >> 4) & 1) * 8 + (lane & 7);
        int cbb = ((lane >> 3) & 1) * 16;
#pragma unroll
        for (int p = 0; p < 4; p++)
            offB[p] = (uint32_t)((wn * 64 + p * 16 + rb) * 80 + cbb);
    }

    float acc[2][8][4] = {};
    int jrow = jc + lrow;
    const int bsz = (jrow < VOC) ? 16 : 0;        // cp.async zero-fill OOB rows
    const __nv_bfloat16* arow = zih + (size_t)(t0 + lrow) * LDIM + eo;
    const __nv_bfloat16* brow = zch + (size_t)jrow * LDIM + eo;
    const uint32_t ldst = (uint32_t)(lrow * 80 + eo * 2);

    // prologue: async stage 0
    cp16(stA[0] + ldst,      arow,     16);
    cp16(stA[0] + ldst + 16, arow + 8, 16);
    cp16(stB[0] + ldst,      brow,     bsz);
    cp16(stB[0] + ldst + 16, brow + 8, bsz);
    CP_COMMIT();

#pragma unroll
    for (int s = 0; s < 8; s++) {            // 8 stages of 32 k-dims
        CP_WAIT0();
        __syncthreads();
        if (s < 7) {                         // async prefetch next stage
            int ko = (s + 1) * 32;
            uint32_t dA = stA[(s + 1) & 1] + ldst;
            uint32_t dB = stB[(s + 1) & 1] + ldst;
            cp16(dA,      arow + ko,     16);
            cp16(dA + 16, arow + ko + 8, 16);
            cp16(dB,      brow + ko,     bsz);
            cp16(dB + 16, brow + ko + 8, bsz);
            CP_COMMIT();
        }
        const uint32_t sA = stA[s & 1], sB = stB[s & 1];
#pragma unroll
        for (int ks = 0; ks < 2; ks++) {
            unsigned a0[4], a1[4];
            ldsm_x4(sA + offA[0] + ks * 32, a0);
            ldsm_x4(sA + offA[1] + ks * 32, a1);
#pragma unroll
            for (int p = 0; p < 4; p++) {
                unsigned bb[4];
                ldsm_x4(sB + offB[p] + ks * 32, bb);
                mma_bf16(acc[0][2*p],     a0, bb);
                mma_bf16(acc[0][2*p + 1], a0, bb + 2);
                mma_bf16(acc[1][2*p],     a1, bb);
                mma_bf16(acc[1][2*p + 1], a1, bb + 2);
            }
        }
    }

    // ---- epilogue: cvt bf16, store, packed block-max (no syncs needed) ----
    const int colbase = wn * 64 + tig * 2;
#pragma unroll
    for (int mi = 0; mi < 2; mi++)
#pragma unroll
    for (int h = 0; h < 2; h++) {
        int row_l = wm * 32 + mi * 16 + grp + h * 8;
        size_t rowoff = (size_t)(t0 + row_l) * VOCP;
        unsigned p[8];
#pragma unroll
        for (int ni = 0; ni < 8; ni++) {
            float2 f2 = make_float2(acc[mi][ni][2*h], acc[mi][ni][2*h + 1]);
            __nv_bfloat162 bb = __float22bfloat162_rn(f2);   // .x -> low half
            p[ni] = *(unsigned*)&bb;
        }
        if (jc + 128 > VOC) {        // mask tail columns with bf16 -inf
#pragma unroll
            for (int ni = 0; ni < 8; ni++) {
                int j = jc + colbase + ni * 8;
                if (j >= VOC)     p[ni] = (p[ni] & 0xFFFF0000u) | 0x0000FF80u;
                if (j + 1 >= VOC) p[ni] = (p[ni] & 0x0000FFFFu) | 0xFF800000u;
            }
        }
#pragma unroll
        for (int ni = 0; ni < 8; ni++)
            *(unsigned*)(scores + rowoff + jc + colbase + ni * 8) = p[ni];
        // packed max tree over this thread's 16 cols, then across tig quad
        __nv_bfloat162 m = *(__nv_bfloat162*)&p[0];
#pragma unroll
        for (int ni = 1; ni < 8; ni++) m = __hmax2(m, *(__nv_bfloat162*)&p[ni]);
        unsigned mu = *(unsigned*)&m;
        unsigned o1 = __shfl_xor_sync(0xFFFFFFFFu, mu, 1);
        m = __hmax2(m, *(__nv_bfloat162*)&o1);
        mu = *(unsigned*)&m;
        unsigned o2 = __shfl_xor_sync(0xFFFFFFFFu, mu, 2);
        m = __hmax2(m, *(__nv_bfloat162*)&o2);
        if (tig == 0) {
            __nv_bfloat16 ms = __hmax(m.x, m.y);
            bmax[(size_t)(t0 + row_l) * BMAXP + (jc >> 6) + wn] = ms;
        }
    }
}

// ---------------- K2: block select + candidate prune + exact top-4 --------
// one warp per token
__global__ void __launch_bounds__(128)
select_k(const __nv_bfloat16* __restrict__ bmax, const __nv_bfloat16* __restrict__ scores,
         const float* __restrict__ zi, const float* __restrict__ zc)
{
    __shared__ int scand[4][NCAND];
    const int wl = threadIdx.x >> 5;
    const int t = (blockIdx.x * blockDim.x + threadIdx.x) >> 5;
    const int lane = threadIdx.x & 31;
    if (t >= NTOK) return;

    // Phase A: lane-local top-8 of 786 blockmaxes
    float lv[8]; int lb[8];
#pragma unroll
    for (int k = 0; k < 8; k++) { lv[k] = -FLT_MAX; lb[k] = INT_MAX; }
    const __nv_bfloat16* bm = bmax + (size_t)t * BMAXP;
#pragma unroll
    for (int k = 0; k < 25; k++) {
        int b = lane + 32 * k;
        if (b < NBLK) {
            float v = __bfloat162float(bm[b]);
            if (v >= lv[7]) insK<8>(v, b, lv, lb);
        }
    }
    // extract top-16 blocks (warp-wide argmax, owner pops)
    int blk[16];
#pragma unroll
    for (int r = 0; r < 16; r++) {
        float cv = lv[0]; int cb = lb[0];
#pragma unroll
        for (int off = 16; off > 0; off >>= 1) {
            float ov = __shfl_xor_sync(0xFFFFFFFFu, cv, off);
            int   ob = __shfl_xor_sync(0xFFFFFFFFu, cb, off);
            if (better(ov, ob, cv, cb)) { cv = ov; cb = ob; }
        }
        blk[r] = cb;
        if (lb[0] == cb) {
#pragma unroll
            for (int k = 0; k < 7; k++) { lv[k] = lv[k+1]; lb[k] = lb[k+1]; }
            lv[7] = -FLT_MAX; lb[7] = INT_MAX;
        }
    }

    // Phase B: lane-local top-12 over the 16 blocks' 1024 bf16 scores
    float cv12[12]; int ci12[12];
#pragma unroll
    for (int k = 0; k < 12; k++) { cv12[k] = -FLT_MAX; ci12[k] = INT_MAX; }
    const __nv_bfloat16* srow = scores + (size_t)t * VOCP;
#pragma unroll
    for (int r = 0; r < 16; r++) {
        int j0 = blk[r] * 64 + lane * 2;
        unsigned u = *(const unsigned*)(srow + j0);
        __nv_bfloat162 b2 = *(__nv_bfloat162*)&u;
        float f0 = __bfloat162float(b2.x);
        float f1 = __bfloat162float(b2.y);
        if (f0 >= cv12[11]) insK<12>(f0, j0,     cv12, ci12);
        if (f1 >= cv12[11]) insK<12>(f1, j0 + 1, cv12, ci12);
    }
    // Phase C: extract top-24 candidates into smem
#pragma unroll
    for (int r = 0; r < NCAND; r++) {
        float cv = cv12[0]; int cb = ci12[0];
#pragma unroll
        for (int off = 16; off > 0; off >>= 1) {
            float ov = __shfl_xor_sync(0xFFFFFFFFu, cv, off);
            int   ob = __shfl_xor_sync(0xFFFFFFFFu, cb, off);
            if (better(ov, ob, cv, cb)) { cv = ov; cb = ob; }
        }
        if (lane == 0) scand[wl][r] = cb;
        if (ci12[0] == cb) {
#pragma unroll
            for (int k = 0; k < 11; k++) { cv12[k] = cv12[k+1]; ci12[k] = ci12[k+1]; }
            cv12[11] = -FLT_MAX; ci12[11] = INT_MAX;
        }
    }
    __syncwarp();

    // Phase D: exact fp32 rescore of 24 candidates -> top-4 + histogram
    const float* zr = zi + (size_t)t * LDIM;
    float a[8];
#pragma unroll
    for (int i = 0; i < 8; i++) a[i] = zr[lane + 32 * i];
    float tv[4] = {-FLT_MAX, -FLT_MAX, -FLT_MAX, -FLT_MAX};
    int   ti[4] = {INT_MAX, INT_MAX, INT_MAX, INT_MAX};
    for (int c = 0; c < NCAND; c += 2) {
        int j0c = scand[wl][c], j1c = scand[wl][c + 1];
        const float* b0 = zc + (size_t)j0c * LDIM;
        const float* b1 = zc + (size_t)j1c * LDIM;
        float s0 = 0.f, s1 = 0.f;
#pragma unroll
        for (int i = 0; i < 8; i++) {
            s0 += a[i] * b0[lane + 32 * i];
            s1 += a[i] * b1[lane + 32 * i];
        }
#pragma unroll
        for (int off = 16; off > 0; off >>= 1) {
            s0 += __shfl_xor_sync(0xFFFFFFFFu, s0, off);
            s1 += __shfl_xor_sync(0xFFFFFFFFu, s1, off);
        }
        insK<4>(s0, j0c, tv, ti);
        insK<4>(s1, j1c, tv, ti);
    }
    if (lane == 0) {
#pragma unroll
        for (int k = 0; k < 4; k++) {
            g_idx[t * 4 + k] = ti[k];
            atomicAdd(&g_counts[ti[k]], 1);
        }
    }
}

// ---------------- quantize + STE out + mse1 --------------------------------
__global__ void quant_k(const float* __restrict__ x, const float* __restrict__ cb,
                        float* __restrict__ out)
{
    int w = (blockIdx.x * blockDim.x + threadIdx.x) >> 5;   // token
    int lane = threadIdx.x & 31;
    if (w >= NTOK) return;
    const float* c0 = cb + (size_t)g_idx[w * 4 + 0] * DDIM;
    const float* c1 = cb + (size_t)g_idx[w * 4 + 1] * DDIM;
    const float* c2 = cb + (size_t)g_idx[w * 4 + 2] * DDIM;
    const float* c3 = cb + (size_t)g_idx[w * 4 + 3] * DDIM;
    double s = 0.0;
    for (int c = lane; c < DDIM; c += 32) {
        float qv = (((c0[c] + c1[c]) + c2[c]) + c3[c]) * 0.25f;
        float xv = x[(size_t)w * DDIM + c];
        float d = qv - xv;
        out[(size_t)w * DDIM + c] = xv + d;     // x + (q - x), matches STE
        s += (double)d * (double)d;
    }
#pragma unroll
    for (int off = 16; off > 0; off >>= 1)
        s += __shfl_down_sync(0xFFFFFFFFu, s, off);
    if (lane == 0) atomicAdd(&g_mse1, s);
}

// ---------------- mse2 via zc reuse: q@Wc+b == mean_k zc_pre[j_k] ----------
__global__ void mse2_k(const float* __restrict__ zc, const float* __restrict__ rn,
                       const float* __restrict__ zi_pre)
{
    int t = (blockIdx.x * blockDim.x + threadIdx.x) >> 5;
    int lane = threadIdx.x & 31;
    if (t >= NTOK) return;
    int j0 = g_idx[t * 4 + 0], j1 = g_idx[t * 4 + 1];
    int j2 = g_idx[t * 4 + 2], j3 = g_idx[t * 4 + 3];
    float w0 = 0.25f * rn[j0], w1 = 0.25f * rn[j1];
    float w2 = 0.25f * rn[j2], w3 = 0.25f * rn[j3];
    const float* z0 = zc + (size_t)j0 * LDIM;
    const float* z1 = zc + (size_t)j1 * LDIM;
    const float* z2 = zc + (size_t)j2 * LDIM;
    const float* z3 = zc + (size_t)j3 * LDIM;
    const float* rp = zi_pre + (size_t)t * LDIM;
    double s = 0.0;
#pragma unroll
    for (int i = 0; i < 8; i++) {
        int c = lane + 32 * i;
        float v = z0[c] * w0 + z1[c] * w1 + z2[c] * w2 + z3[c] * w3 - rp[c];
        s += (double)v * (double)v;
    }
#pragma unroll
    for (int off = 16; off > 0; off >>= 1)
        s += __shfl_down_sync(0xFFFFFFFFu, s, off);
    if (lane == 0) atomicAdd(&g_mse2, s);
}

// ---------------- entropy / usage ------------------------------------------
__global__ void ent_k()
{
    int i0 = blockIdx.x * blockDim.x + threadIdx.x;
    double e = 0.0; int nz = 0;
    for (int i = i0; i < VOC; i += gridDim.x * blockDim.x) {
        int c = g_counts[i];
        if (c > 0) {
            float p = (float)c * (1.0f / (NTOK * KSEL));
            e += (double)(p * logf(p + 1e-10f));
            nz++;
        }
    }
#pragma unroll
    for (int off = 16; off > 0; off >>= 1) {
        e  += __shfl_down_sync(0xFFFFFFFFu, e, off);
        nz += __shfl_down_sync(0xFFFFFFFFu, nz, off);
    }
    if ((threadIdx.x & 31) == 0) { atomicAdd(&g_ent, e); atomicAdd(&g_nz, nz); }
}

// ---------------- finalize scalars -----------------------------------------
__global__ void fin_k(float* __restrict__ out3)
{
    float lp = (float)(-g_ent);
    float mse1 = (float)(g_mse1 / ((double)NTOK * DDIM));
    float mse2 = (float)(g_mse2 / ((double)NTOK * LDIM));
    float loss = 1.25f * mse1 + 1.25f * mse2 + 0.1f * lp;
    out3[0] = loss;
    out3[1] = expf(lp);
    out3[2] = (float)g_nz / (float)VOC / (float)KSEL;
}

// ---------------- launch ----------------------------------------------------
static float* sym_f(const void* s) { void* p = nullptr; cudaGetSymbolAddress(&p, s); return (float*)p; }
static __nv_bfloat16* sym_b(const void* s) { void* p = nullptr; cudaGetSymbolAddress(&p, s); return (__nv_bfloat16*)p; }

extern "C" void kernel_launch(void* const* d_in, const int* in_sizes, int n_in,
                              void* d_out, int out_size)
{
    const float* x  = (const float*)d_in[0];
    const float* cb = (const float*)d_in[1];
    const float* Wi = (const float*)d_in[2];
    const float* bi = (const float*)d_in[3];
    const float* Wc = (const float*)d_in[4];
    const float* bc = (const float*)d_in[5];
    float* out = (float*)d_out;

    float* zi_pre = sym_f(g_zi_pre);
    float* zi     = sym_f(g_zi);
    float* zc     = sym_f(g_zc);
    float* zcn    = sym_f(g_zcn);
    __nv_bfloat16* zih = sym_b(g_zih);
    __nv_bfloat16* zch = sym_b(g_zch);
    __nv_bfloat16* scores = sym_b(g_scores);
    __nv_bfloat16* bmax   = sym_b(g_bmax);

    init_k<<<64, 256>>>();
    // zi_pre = x @ W_in + b_in ; zi = l2n(zi_pre) (+ bf16 copy)
    gemm_k<<<dim3(NTOK / 64, LDIM / 64), 256>>>(x, Wi, bi, zi_pre, NTOK);
    norm_k<<<NTOK / 8, 256>>>(zi_pre, zi, zih, nullptr, NTOK);
    // zc = l2n(codebook @ W_code + b_code) (+ bf16 copy + recip norm)
    gemm_k<<<dim3((VOC + 63) / 64, LDIM / 64), 256>>>(cb, Wc, bc, zc, VOC);
    norm_k<<<(VOC + 7) / 8, 256>>>(zc, zc, zch, zcn, VOC);
    // K1: bf16 MMA scores (cp.async + ldmatrix) -> gmem + blockmax
    score_mma<<<dim3(NTOK / 128, VOCP / 128), 256>>>(zih, zch, scores, bmax);
    // K2: block-select + prune + exact top-4 + histogram
    select_k<<<NTOK / 4, 128>>>(bmax, scores, zi, zc);
    // quantize + STE output + mse1
    quant_k<<<NTOK / 8, 256>>>(x, cb, out);
    // mse2 without a GEMM: q@Wc+b == mean of selected zc_pre rows
    mse2_k<<<NTOK / 8, 256>>>(zc, zcn, zi_pre);
    ent_k<<<64, 256>>>();
    fin_k<<<1, 1>>>(out + (size_t)NTOK * DDIM);
}

// round 11
// speedup vs baseline: 6.7065x; 1.3825x over previous
#include <cuda_runtime.h>
#include <cuda_bf16.h>
#include <math.h>
#include <float.h>
#include <limits.h>
#include <stdint.h>

// Problem constants
#define NTOK 4096      // B*S
#define DDIM 768
#define LDIM 256
#define VOC  50265
#define VOCP 50304     // 393 tiles of 128
#define NBLK 786       // 64-code blocks (VOCP/64)
#define BMAXP 788      // padded row
#define KSEL 4
#define NCAND 24

// ---------------- scratch (device globals; no allocations) ----------------
__device__ float  g_zi_pre[NTOK * LDIM];      // x@W_in+b (kept for mse2 ref)
__device__ float  g_zi[NTOK * LDIM];          // normalized
__device__ float  g_zc[VOC * LDIM];           // normalized latent codebook
__device__ float  g_zcn[VOC];                 // reciprocal norm: zc_pre = zc * g_zcn
__device__ __nv_bfloat16 g_zih[NTOK * LDIM];
__device__ __nv_bfloat16 g_zch[VOC * LDIM];
__device__ __nv_bfloat16 g_cbh[VOC * DDIM];   // bf16 hi split of codebook
__device__ __nv_bfloat16 g_cbl[VOC * DDIM];   // bf16 lo split of codebook
__device__ __nv_bfloat16 g_wth[LDIM * DDIM];  // W_code^T hi (n-major, k-contig)
__device__ __nv_bfloat16 g_wtl[LDIM * DDIM];  // W_code^T lo
__device__ __nv_bfloat16 g_scores[(size_t)NTOK * VOCP];   // all approx scores
__device__ __nv_bfloat16 g_bmax[(size_t)NTOK * BMAXP];    // per-64-block max
__device__ int    g_idx[NTOK * KSEL];
__device__ int    g_counts[VOC];
__device__ double g_mse1, g_mse2, g_ent;
__device__ int    g_nz;

// ---------------- helpers ----------------
__device__ __forceinline__ uint32_t smem_u32(const void* p) {
    uint32_t a;
    asm("{ .reg .u64 t; cvta.to.shared.u64 t, %1; cvt.u32.u64 %0, t; }" : "=r"(a) : "l"(p));
    return a;
}
__device__ __forceinline__ bool better(float v, int j, float v2, int j2) {
    return (v > v2) || (v == v2 && j < j2);
}
template <int K>
__device__ __forceinline__ void insK(float v, int j, float tv[K], int ti[K]) {
    if (!better(v, j, tv[K-1], ti[K-1])) return;
    tv[K-1] = v; ti[K-1] = j;
#pragma unroll
    for (int k = K-1; k > 0; k--) {
        if (better(tv[k], ti[k], tv[k-1], ti[k-1])) {
            float fv = tv[k]; tv[k] = tv[k-1]; tv[k-1] = fv;
            int   fi = ti[k]; ti[k] = ti[k-1]; ti[k-1] = fi;
        }
    }
}

// ---------------- bf16 mma + ldmatrix + cp.async helpers ----------------
__device__ __forceinline__ void mma_bf16(float d[4], const unsigned a[4], const unsigned b[2]) {
    asm("mma.sync.aligned.m16n8k16.row.col.f32.bf16.bf16.f32 "
        "{%0,%1,%2,%3},{%4,%5,%6,%7},{%8,%9},{%0,%1,%2,%3};"
        : "+f"(d[0]), "+f"(d[1]), "+f"(d[2]), "+f"(d[3])
        : "r"(a[0]), "r"(a[1]), "r"(a[2]), "r"(a[3]), "r"(b[0]), "r"(b[1]));
}
__device__ __forceinline__ void ldsm_x4(uint32_t addr, unsigned r[4]) {
    asm volatile("ldmatrix.sync.aligned.m8n8.x4.shared.b16 {%0,%1,%2,%3}, [%4];"
        : "=r"(r[0]), "=r"(r[1]), "=r"(r[2]), "=r"(r[3]) : "r"(addr));
}
__device__ __forceinline__ void cp16(uint32_t dst, const void* src, int ssz) {
    asm volatile("cp.async.cg.shared.global [%0], [%1], 16, %2;"
        :: "r"(dst), "l"(src), "r"(ssz) : "memory");
}
#define CP_COMMIT() asm volatile("cp.async.commit_group;" ::: "memory")
#define CP_WAIT0()  asm volatile("cp.async.wait_group 0;" ::: "memory")

// ---------------- init ----------------
__global__ void init_k() {
    int i = blockIdx.x * blockDim.x + threadIdx.x;
    for (int v = i; v < VOC; v += gridDim.x * blockDim.x) g_counts[v] = 0;
    if (i == 0) { g_mse1 = 0.0; g_mse2 = 0.0; g_ent = 0.0; g_nz = 0; }
}

// ---------------- bf16 hi/lo split of codebook (streaming) -----------------
__global__ void splitcb_k(const float4* __restrict__ in, uint2* __restrict__ oh,
                          uint2* __restrict__ ol, int n4)
{
    int i = blockIdx.x * blockDim.x + threadIdx.x;
    int stride = gridDim.x * blockDim.x;
    for (; i < n4; i += stride) {
        float4 v = in[i];
        __nv_bfloat16 h0 = __float2bfloat16(v.x);
        __nv_bfloat16 h1 = __float2bfloat16(v.y);
        __nv_bfloat16 h2 = __float2bfloat16(v.z);
        __nv_bfloat16 h3 = __float2bfloat16(v.w);
        __nv_bfloat16 l0 = __float2bfloat16(v.x - __bfloat162float(h0));
        __nv_bfloat16 l1 = __float2bfloat16(v.y - __bfloat162float(h1));
        __nv_bfloat16 l2 = __float2bfloat16(v.z - __bfloat162float(h2));
        __nv_bfloat16 l3 = __float2bfloat16(v.w - __bfloat162float(h3));
        __nv_bfloat162 hp0 = {h0, h1}, hp1 = {h2, h3};
        __nv_bfloat162 lp0 = {l0, l1}, lp1 = {l2, l3};
        uint2 uh, ul;
        uh.x = *(unsigned*)&hp0; uh.y = *(unsigned*)&hp1;
        ul.x = *(unsigned*)&lp0; ul.y = *(unsigned*)&lp1;
        oh[i] = uh; ol[i] = ul;
    }
}

// ---------------- transpose + split W_code: WcT[n][k] = Wc[k][n] -----------
__global__ void wsplit_k(const float* __restrict__ Wc,
                         __nv_bfloat16* __restrict__ wth, __nv_bfloat16* __restrict__ wtl)
{
    int idx = blockIdx.x * blockDim.x + threadIdx.x;
    if (idx >= LDIM * DDIM) return;
    int n = idx / DDIM, k = idx - n * DDIM;
    float v = Wc[k * LDIM + n];
    __nv_bfloat16 h = __float2bfloat16(v);
    wth[idx] = h;
    wtl[idx] = __float2bfloat16(v - __bfloat162float(h));
}

// ---------------- GEMM (R1 proven): C[M,256] = A[M,768] @ W + bias --------
// (still used for the small zi projection; exact fp32)
__global__ void __launch_bounds__(256, 2)
gemm_k(const float* __restrict__ A, const float* __restrict__ W,
       const float* __restrict__ bias, float* __restrict__ C, int M)
{
    __shared__ float As[32][68];   // k-major: As[k][m]
    __shared__ float Ws[32][68];   // Ws[k][n]
    const int tid = threadIdx.x;
    const int m0 = blockIdx.x * 64, n0 = blockIdx.y * 64;
    const int tx = tid & 15, ty = tid >> 4;

    float acc[4][4] = {};
    for (int c0 = 0; c0 < DDIM; c0 += 32) {
#pragma unroll
        for (int t = 0; t < 2; t++) {            // A tile -> transposed store
            int li = tid * 2 + t;
            int row = li >> 3, kq = li & 7;
            float4 v = make_float4(0.f, 0.f, 0.f, 0.f);
            if (m0 + row < M)
                v = *(const float4*)&A[(size_t)(m0 + row) * DDIM + c0 + kq * 4];
            As[kq*4+0][row] = v.x; As[kq*4+1][row] = v.y;
            As[kq*4+2][row] = v.z; As[kq*4+3][row] = v.w;
        }
#pragma unroll
        for (int t = 0; t < 2; t++) {            // W tile -> direct store
            int li = tid * 2 + t;
            int r = li >> 4, nq = li & 15;
            float4 v = *(const float4*)&W[(size_t)(c0 + r) * LDIM + n0 + nq * 4];
            *(float4*)&Ws[r][nq * 4] = v;
        }
        __syncthreads();
#pragma unroll
        for (int kk = 0; kk < 32; kk++) {
            float4 a4 = *(float4*)&As[kk][ty * 4];
            float4 b4 = *(float4*)&Ws[kk][tx * 4];
            float av[4] = {a4.x, a4.y, a4.z, a4.w};
            float bv[4] = {b4.x, b4.y, b4.z, b4.w};
#pragma unroll
            for (int i = 0; i < 4; i++)
#pragma unroll
                for (int j = 0; j < 4; j++)
                    acc[i][j] += av[i] * bv[j];
        }
        __syncthreads();
    }
#pragma unroll
    for (int i = 0; i < 4; i++) {
        int row = m0 + ty * 4 + i;
        if (row < M) {
#pragma unroll
            for (int j = 0; j < 4; j++) {
                int col = n0 + tx * 4 + j;
                C[(size_t)row * LDIM + col] = acc[i][j] + bias[col];
            }
        }
    }
}

// ---------------- zc GEMM via 3-product bf16-split tensor MMA --------------
// C[row,col] = sum_k (cbh+cbl)[row,k] * (wth+wtl)[col,k] + bias[col]
// products: hh + hl + lh (ll dropped: ~2^-16/term, incoherent => ~3e-7 abs)
// grid (393, 2), 256 threads, dynamic smem 81920 (2 CTA/SM).
__global__ void __launch_bounds__(256, 2)
zc_mma(const __nv_bfloat16* __restrict__ cbh, const __nv_bfloat16* __restrict__ cbl,
       const __nv_bfloat16* __restrict__ wth, const __nv_bfloat16* __restrict__ wtl,
       const float* __restrict__ bias, float* __restrict__ C)
{
    extern __shared__ __align__(16) char dynbuf[];
    const int tid = threadIdx.x;
    const int w = tid >> 5, lane = tid & 31;
    const int grp = lane >> 2, tig = lane & 3;
    const int wm = w >> 1, wn = w & 1;            // 4 x 2 warp grid
    const int m0 = blockIdx.x * 128;
    const int n0 = blockIdx.y * 128;
    const int lrow = tid >> 1;                    // loader row 0..127
    const int eo   = (tid & 1) * 16;

    const uint32_t sm0 = smem_u32(dynbuf);
    const uint32_t ldst = (uint32_t)(lrow * 80 + eo * 2);

    // ldmatrix per-thread offsets (80B pitch; same proven layout as score_mma)
    uint32_t offA[2], offB[4];
    {
        int la = lane & 15, ha = lane >> 4;
#pragma unroll
        for (int mi = 0; mi < 2; mi++)
            offA[mi] = (uint32_t)((wm * 32 + mi * 16 + la) * 80 + ha * 16);
        int rb = ((lane >> 4) & 1) * 8 + (lane & 7);
        int cbb = ((lane >> 3) & 1) * 16;
#pragma unroll
        for (int p = 0; p < 4; p++)
            offB[p] = (uint32_t)((wn * 64 + p * 16 + rb) * 80 + cbb);
    }

    float acc[2][8][4] = {};
    const int asz = (m0 + lrow < VOC) ? 16 : 0;   // zero-fill OOB codebook rows
    const __nv_bfloat16* ah_src = cbh + (size_t)(m0 + lrow) * DDIM + eo;
    const __nv_bfloat16* al_src = cbl + (size_t)(m0 + lrow) * DDIM + eo;
    const __nv_bfloat16* bh_src = wth + (size_t)(n0 + lrow) * DDIM + eo;
    const __nv_bfloat16* bl_src = wtl + (size_t)(n0 + lrow) * DDIM + eo;

    // prologue: async stage 0 (buffers: Ah,Al,Bh,Bl @ 10240 each; +40960/buf)
    {
        uint32_t b = sm0;
        cp16(b + ldst,              ah_src,     asz);
        cp16(b + ldst + 16,         ah_src + 8, asz);
        cp16(b + 10240 + ldst,      al_src,     asz);
        cp16(b + 10240 + ldst + 16, al_src + 8, asz);
        cp16(b + 20480 + ldst,      bh_src,     16);
        cp16(b + 20480 + ldst + 16, bh_src + 8, 16);
        cp16(b + 30720 + ldst,      bl_src,     16);
        cp16(b + 30720 + ldst + 16, bl_src + 8, 16);
        CP_COMMIT();
    }

    for (int s = 0; s < 24; s++) {           // 24 stages of 32 k-dims
        CP_WAIT0();
        __syncthreads();
        if (s < 23) {
            int ko = (s + 1) * 32;
            uint32_t b = sm0 + (uint32_t)(((s + 1) & 1) * 40960);
            cp16(b + ldst,              ah_src + ko,     asz);
            cp16(b + ldst + 16,         ah_src + ko + 8, asz);
            cp16(b + 10240 + ldst,      al_src + ko,     asz);
            cp16(b + 10240 + ldst + 16, al_src + ko + 8, asz);
            cp16(b + 20480 + ldst,      bh_src + ko,     16);
            cp16(b + 20480 + ldst + 16, bh_src + ko + 8, 16);
            cp16(b + 30720 + ldst,      bl_src + ko,     16);
            cp16(b + 30720 + ldst + 16, bl_src + ko + 8, 16);
            CP_COMMIT();
        }
        uint32_t bb_ = sm0 + (uint32_t)((s & 1) * 40960);
        uint32_t sAh = bb_, sAl = bb_ + 10240, sBh = bb_ + 20480, sBl = bb_ + 30720;
#pragma unroll
        for (int ks = 0; ks < 2; ks++) {
            unsigned ah0[4], ah1[4], al0[4], al1[4];
            ldsm_x4(sAh + offA[0] + ks * 32, ah0);
            ldsm_x4(sAh + offA[1] + ks * 32, ah1);
            ldsm_x4(sAl + offA[0] + ks * 32, al0);
            ldsm_x4(sAl + offA[1] + ks * 32, al1);
#pragma unroll
            for (int p = 0; p < 4; p++) {
                unsigned bh[4], bl[4];
                ldsm_x4(sBh + offB[p] + ks * 32, bh);
                ldsm_x4(sBl + offB[p] + ks * 32, bl);
                mma_bf16(acc[0][2*p],     ah0, bh);
                mma_bf16(acc[0][2*p + 1], ah0, bh + 2);
                mma_bf16(acc[1][2*p],     ah1, bh);
                mma_bf16(acc[1][2*p + 1], ah1, bh + 2);
                mma_bf16(acc[0][2*p],     ah0, bl);
                mma_bf16(acc[0][2*p + 1], ah0, bl + 2);
                mma_bf16(acc[1][2*p],     ah1, bl);
                mma_bf16(acc[1][2*p + 1], ah1, bl + 2);
                mma_bf16(acc[0][2*p],     al0, bh);
                mma_bf16(acc[0][2*p + 1], al0, bh + 2);
                mma_bf16(acc[1][2*p],     al1, bh);
                mma_bf16(acc[1][2*p + 1], al1, bh + 2);
            }
        }
    }

    // epilogue: +bias, fp32 store
#pragma unroll
    for (int mi = 0; mi < 2; mi++)
#pragma unroll
    for (int h = 0; h < 2; h++) {
        int row = m0 + wm * 32 + mi * 16 + grp + h * 8;
        if (row < VOC) {
#pragma unroll
            for (int ni = 0; ni < 8; ni++) {
                int col = n0 + wn * 64 + ni * 8 + tig * 2;
                float2 v;
                v.x = acc[mi][ni][2*h]     + bias[col];
                v.y = acc[mi][ni][2*h + 1] + bias[col + 1];
                *(float2*)&C[(size_t)row * LDIM + col] = v;
            }
        }
    }
}

// ---------------- row L2-normalize, fused bf16 emit (+ optional recip) -----
__global__ void norm_k(const float* __restrict__ in, float* __restrict__ out,
                       __nv_bfloat16* __restrict__ outh, float* __restrict__ rnorm, int M)
{
    int w = (blockIdx.x * blockDim.x + threadIdx.x) >> 5;
    int lane = threadIdx.x & 31;
    if (w >= M) return;
    const float* r = in + (size_t)w * LDIM;
    float vals[8];
    float s = 0.f;
#pragma unroll
    for (int i = 0; i < 8; i++) { vals[i] = r[lane + 32 * i]; s += vals[i] * vals[i]; }
#pragma unroll
    for (int off = 16; off > 0; off >>= 1)
        s += __shfl_xor_sync(0xFFFFFFFFu, s, off);
    float t = s + 1e-12f;
    float sc = rsqrtf(t);
    sc = sc * (1.5f - 0.5f * t * sc * sc);   // Newton: ~1 ulp
    float* o = out + (size_t)w * LDIM;
    __nv_bfloat16* oh = outh + (size_t)w * LDIM;
#pragma unroll
    for (int i = 0; i < 8; i++) {
        float v = vals[i] * sc;
        o[lane + 32 * i] = v;
        oh[lane + 32 * i] = __float2bfloat16(v);
    }
    if (rnorm && lane == 0) rnorm[w] = 1.0f / sc;
}

// ---------------- K1: MMA scores -> bf16 store + 64-block max --------------
// grid (NTOK/128, VOCP/128). cp.async double-buffer; ldmatrix fragments.
__global__ void __launch_bounds__(256, 2)
score_mma(const __nv_bfloat16* __restrict__ zih, const __nv_bfloat16* __restrict__ zch,
          __nv_bfloat16* __restrict__ scores, __nv_bfloat16* __restrict__ bmax)
{
    __shared__ __align__(16) char smembuf[40960];
    const int tid = threadIdx.x;
    const int w = tid >> 5, lane = tid & 31;
    const int grp = lane >> 2, tig = lane & 3;
    const int wm = w >> 1, wn = w & 1;            // 4 x 2 warp grid
    const int t0 = blockIdx.x * 128;
    const int jc = blockIdx.y * 128;

    const int lrow = tid >> 1;                    // loader row 0..127
    const int eo   = (tid & 1) * 16;

    const uint32_t sm0 = smem_u32(smembuf);
    const uint32_t stA[2] = {sm0,         sm0 + 10240};
    const uint32_t stB[2] = {sm0 + 20480, sm0 + 30720};

    // ldmatrix per-thread offsets (80B pitch rows; conflict-free phases)
    uint32_t offA[2], offB[4];
    {
        int la = lane & 15, ha = lane >> 4;       // A: row sel, k half
#pragma unroll
        for (int mi = 0; mi < 2; mi++)
            offA[mi] = (uint32_t)((wm * 32 + mi * 16 + la) * 80 + ha * 16);
        int rb = ((lane >> 4) & 1) * 8 + (lane & 7);
        int cbb = ((lane >> 3) & 1) * 16;
#pragma unroll
        for (int p = 0; p < 4; p++)
            offB[p] = (uint32_t)((wn * 64 + p * 16 + rb) * 80 + cbb);
    }

    float acc[2][8][4] = {};
    int jrow = jc + lrow;
    const int bsz = (jrow < VOC) ? 16 : 0;        // cp.async zero-fill OOB rows
    const __nv_bfloat16* arow = zih + (size_t)(t0 + lrow) * LDIM + eo;
    const __nv_bfloat16* brow = zch + (size_t)jrow * LDIM + eo;
    const uint32_t ldst = (uint32_t)(lrow * 80 + eo * 2);

    // prologue: async stage 0
    cp16(stA[0] + ldst,      arow,     16);
    cp16(stA[0] + ldst + 16, arow + 8, 16);
    cp16(stB[0] + ldst,      brow,     bsz);
    cp16(stB[0] + ldst + 16, brow + 8, bsz);
    CP_COMMIT();

#pragma unroll
    for (int s = 0; s < 8; s++) {            // 8 stages of 32 k-dims
        CP_WAIT0();
        __syncthreads();
        if (s < 7) {                         // async prefetch next stage
            int ko = (s + 1) * 32;
            uint32_t dA = stA[(s + 1) & 1] + ldst;
            uint32_t dB = stB[(s + 1) & 1] + ldst;
            cp16(dA,      arow + ko,     16);
            cp16(dA + 16, arow + ko + 8, 16);
            cp16(dB,      brow + ko,     bsz);
            cp16(dB + 16, brow + ko + 8, bsz);
            CP_COMMIT();
        }
        const uint32_t sA = stA[s & 1], sB = stB[s & 1];
#pragma unroll
        for (int ks = 0; ks < 2; ks++) {
            unsigned a0[4], a1[4];
            ldsm_x4(sA + offA[0] + ks * 32, a0);
            ldsm_x4(sA + offA[1] + ks * 32, a1);
#pragma unroll
            for (int p = 0; p < 4; p++) {
                unsigned bb[4];
                ldsm_x4(sB + offB[p] + ks * 32, bb);
                mma_bf16(acc[0][2*p],     a0, bb);
                mma_bf16(acc[0][2*p + 1], a0, bb + 2);
                mma_bf16(acc[1][2*p],     a1, bb);
                mma_bf16(acc[1][2*p + 1], a1, bb + 2);
            }
        }
    }

    // ---- epilogue: cvt bf16, store, packed block-max (no syncs needed) ----
    const int colbase = wn * 64 + tig * 2;
#pragma unroll
    for (int mi = 0; mi < 2; mi++)
#pragma unroll
    for (int h = 0; h < 2; h++) {
        int row_l = wm * 32 + mi * 16 + grp + h * 8;
        size_t rowoff = (size_t)(t0 + row_l) * VOCP;
        unsigned p[8];
#pragma unroll
        for (int ni = 0; ni < 8; ni++) {
            float2 f2 = make_float2(acc[mi][ni][2*h], acc[mi][ni][2*h + 1]);
            __nv_bfloat162 bb = __float22bfloat162_rn(f2);   // .x -> low half
            p[ni] = *(unsigned*)&bb;
        }
        if (jc + 128 > VOC) {        // mask tail columns with bf16 -inf
#pragma unroll
            for (int ni = 0; ni < 8; ni++) {
                int j = jc + colbase + ni * 8;
                if (j >= VOC)     p[ni] = (p[ni] & 0xFFFF0000u) | 0x0000FF80u;
                if (j + 1 >= VOC) p[ni] = (p[ni] & 0x0000FFFFu) | 0xFF800000u;
            }
        }
#pragma unroll
        for (int ni = 0; ni < 8; ni++)
            *(unsigned*)(scores + rowoff + jc + colbase + ni * 8) = p[ni];
        // packed max tree over this thread's 16 cols, then across tig quad
        __nv_bfloat162 m = *(__nv_bfloat162*)&p[0];
#pragma unroll
        for (int ni = 1; ni < 8; ni++) m = __hmax2(m, *(__nv_bfloat162*)&p[ni]);
        unsigned mu = *(unsigned*)&m;
        unsigned o1 = __shfl_xor_sync(0xFFFFFFFFu, mu, 1);
        m = __hmax2(m, *(__nv_bfloat162*)&o1);
        mu = *(unsigned*)&m;
        unsigned o2 = __shfl_xor_sync(0xFFFFFFFFu, mu, 2);
        m = __hmax2(m, *(__nv_bfloat162*)&o2);
        if (tig == 0) {
            __nv_bfloat16 ms = __hmax(m.x, m.y);
            bmax[(size_t)(t0 + row_l) * BMAXP + (jc >> 6) + wn] = ms;
        }
    }
}

// ---------------- K2: block select + candidate prune + exact top-4 --------
// one warp per token
__global__ void __launch_bounds__(128)
select_k(const __nv_bfloat16* __restrict__ bmax, const __nv_bfloat16* __restrict__ scores,
         const float* __restrict__ zi, const float* __restrict__ zc)
{
    __shared__ int scand[4][NCAND];
    const int wl = threadIdx.x >> 5;
    const int t = (blockIdx.x * blockDim.x + threadIdx.x) >> 5;
    const int lane = threadIdx.x & 31;
    if (t >= NTOK) return;

    // Phase A: lane-local top-8 of 786 blockmaxes
    float lv[8]; int lb[8];
#pragma unroll
    for (int k = 0; k < 8; k++) { lv[k] = -FLT_MAX; lb[k] = INT_MAX; }
    const __nv_bfloat16* bm = bmax + (size_t)t * BMAXP;
#pragma unroll
    for (int k = 0; k < 25; k++) {
        int b = lane + 32 * k;
        if (b < NBLK) {
            float v = __bfloat162float(bm[b]);
            if (v >= lv[7]) insK<8>(v, b, lv, lb);
        }
    }
    // extract top-16 blocks (warp-wide argmax, owner pops)
    int blk[16];
#pragma unroll
    for (int r = 0; r < 16; r++) {
        float cv = lv[0]; int cb = lb[0];
#pragma unroll
        for (int off = 16; off > 0; off >>= 1) {
            float ov = __shfl_xor_sync(0xFFFFFFFFu, cv, off);
            int   ob = __shfl_xor_sync(0xFFFFFFFFu, cb, off);
            if (better(ov, ob, cv, cb)) { cv = ov; cb = ob; }
        }
        blk[r] = cb;
        if (lb[0] == cb) {
#pragma unroll
            for (int k = 0; k < 7; k++) { lv[k] = lv[k+1]; lb[k] = lb[k+1]; }
            lv[7] = -FLT_MAX; lb[7] = INT_MAX;
        }
    }

    // Phase B: lane-local top-12 over the 16 blocks' 1024 bf16 scores
    float cv12[12]; int ci12[12];
#pragma unroll
    for (int k = 0; k < 12; k++) { cv12[k] = -FLT_MAX; ci12[k] = INT_MAX; }
    const __nv_bfloat16* srow = scores + (size_t)t * VOCP;
#pragma unroll
    for (int r = 0; r < 16; r++) {
        int j0 = blk[r] * 64 + lane * 2;
        unsigned u = *(const unsigned*)(srow + j0);
        __nv_bfloat162 b2 = *(__nv_bfloat162*)&u;
        float f0 = __bfloat162float(b2.x);
        float f1 = __bfloat162float(b2.y);
        if (f0 >= cv12[11]) insK<12>(f0, j0,     cv12, ci12);
        if (f1 >= cv12[11]) insK<12>(f1, j0 + 1, cv12, ci12);
    }
    // Phase C: extract top-24 candidates into smem
#pragma unroll
    for (int r = 0; r < NCAND; r++) {
        float cv = cv12[0]; int cb = ci12[0];
#pragma unroll
        for (int off = 16; off > 0; off >>= 1) {
            float ov = __shfl_xor_sync(0xFFFFFFFFu, cv, off);
            int   ob = __shfl_xor_sync(0xFFFFFFFFu, cb, off);
            if (better(ov, ob, cv, cb)) { cv = ov; cb = ob; }
        }
        if (lane == 0) scand[wl][r] = cb;
        if (ci12[0] == cb) {
#pragma unroll
            for (int k = 0; k < 11; k++) { cv12[k] = cv12[k+1]; ci12[k] = ci12[k+1]; }
            cv12[11] = -FLT_MAX; ci12[11] = INT_MAX;
        }
    }
    __syncwarp();

    // Phase D: exact fp32 rescore of 24 candidates -> top-4 + histogram
    const float* zr = zi + (size_t)t * LDIM;
    float a[8];
#pragma unroll
    for (int i = 0; i < 8; i++) a[i] = zr[lane + 32 * i];
    float tv[4] = {-FLT_MAX, -FLT_MAX, -FLT_MAX, -FLT_MAX};
    int   ti[4] = {INT_MAX, INT_MAX, INT_MAX, INT_MAX};
    for (int c = 0; c < NCAND; c += 2) {
        int j0c = scand[wl][c], j1c = scand[wl][c + 1];
        const float* b0 = zc + (size_t)j0c * LDIM;
        const float* b1 = zc + (size_t)j1c * LDIM;
        float s0 = 0.f, s1 = 0.f;
#pragma unroll
        for (int i = 0; i < 8; i++) {
            s0 += a[i] * b0[lane + 32 * i];
            s1 += a[i] * b1[lane + 32 * i];
        }
#pragma unroll
        for (int off = 16; off > 0; off >>= 1) {
            s0 += __shfl_xor_sync(0xFFFFFFFFu, s0, off);
            s1 += __shfl_xor_sync(0xFFFFFFFFu, s1, off);
        }
        insK<4>(s0, j0c, tv, ti);
        insK<4>(s1, j1c, tv, ti);
    }
    if (lane == 0) {
#pragma unroll
        for (int k = 0; k < 4; k++) {
            g_idx[t * 4 + k] = ti[k];
            atomicAdd(&g_counts[ti[k]], 1);
        }
    }
}

// ---------------- quantize + STE out + mse1 --------------------------------
__global__ void quant_k(const float* __restrict__ x, const float* __restrict__ cb,
                        float* __restrict__ out)
{
    int w = (blockIdx.x * blockDim.x + threadIdx.x) >> 5;   // token
    int lane = threadIdx.x & 31;
    if (w >= NTOK) return;
    const float* c0 = cb + (size_t)g_idx[w * 4 + 0] * DDIM;
    const float* c1 = cb + (size_t)g_idx[w * 4 + 1] * DDIM;
    const float* c2 = cb + (size_t)g_idx[w * 4 + 2] * DDIM;
    const float* c3 = cb + (size_t)g_idx[w * 4 + 3] * DDIM;
    double s = 0.0;
    for (int c = lane; c < DDIM; c += 32) {
        float qv = (((c0[c] + c1[c]) + c2[c]) + c3[c]) * 0.25f;
        float xv = x[(size_t)w * DDIM + c];
        float d = qv - xv;
        out[(size_t)w * DDIM + c] = xv + d;     // x + (q - x), matches STE
        s += (double)d * (double)d;
    }
#pragma unroll
    for (int off = 16; off > 0; off >>= 1)
        s += __shfl_down_sync(0xFFFFFFFFu, s, off);
    if (lane == 0) atomicAdd(&g_mse1, s);
}

// ---------------- mse2 via zc reuse: q@Wc+b == mean_k zc_pre[j_k] ----------
__global__ void mse2_k(const float* __restrict__ zc, const float* __restrict__ rn,
                       const float* __restrict__ zi_pre)
{
    int t = (blockIdx.x * blockDim.x + threadIdx.x) >> 5;
    int lane = threadIdx.x & 31;
    if (t >= NTOK) return;
    int j0 = g_idx[t * 4 + 0], j1 = g_idx[t * 4 + 1];
    int j2 = g_idx[t * 4 + 2], j3 = g_idx[t * 4 + 3];
    float w0 = 0.25f * rn[j0], w1 = 0.25f * rn[j1];
    float w2 = 0.25f * rn[j2], w3 = 0.25f * rn[j3];
    const float* z0 = zc + (size_t)j0 * LDIM;
    const float* z1 = zc + (size_t)j1 * LDIM;
    const float* z2 = zc + (size_t)j2 * LDIM;
    const float* z3 = zc + (size_t)j3 * LDIM;
    const float* rp = zi_pre + (size_t)t * LDIM;
    double s = 0.0;
#pragma unroll
    for (int i = 0; i < 8; i++) {
        int c = lane + 32 * i;
        float v = z0[c] * w0 + z1[c] * w1 + z2[c] * w2 + z3[c] * w3 - rp[c];
        s += (double)v * (double)v;
    }
#pragma unroll
    for (int off = 16; off > 0; off >>= 1)
        s += __shfl_down_sync(0xFFFFFFFFu, s, off);
    if (lane == 0) atomicAdd(&g_mse2, s);
}

// ---------------- entropy / usage ------------------------------------------
__global__ void ent_k()
{
    int i0 = blockIdx.x * blockDim.x + threadIdx.x;
    double e = 0.0; int nz = 0;
    for (int i = i0; i < VOC; i += gridDim.x * blockDim.x) {
        int c = g_counts[i];
        if (c > 0) {
            float p = (float)c * (1.0f / (NTOK * KSEL));
            e += (double)(p * logf(p + 1e-10f));
            nz++;
        }
    }
#pragma unroll
    for (int off = 16; off > 0; off >>= 1) {
        e  += __shfl_down_sync(0xFFFFFFFFu, e, off);
        nz += __shfl_down_sync(0xFFFFFFFFu, nz, off);
    }
    if ((threadIdx.x & 31) == 0) { atomicAdd(&g_ent, e); atomicAdd(&g_nz, nz); }
}

// ---------------- finalize scalars -----------------------------------------
__global__ void fin_k(float* __restrict__ out3)
{
    float lp = (float)(-g_ent);
    float mse1 = (float)(g_mse1 / ((double)NTOK * DDIM));
    float mse2 = (float)(g_mse2 / ((double)NTOK * LDIM));
    float loss = 1.25f * mse1 + 1.25f * mse2 + 0.1f * lp;
    out3[0] = loss;
    out3[1] = expf(lp);
    out3[2] = (float)g_nz / (float)VOC / (float)KSEL;
}

// ---------------- launch ----------------------------------------------------
static float* sym_f(const void* s) { void* p = nullptr; cudaGetSymbolAddress(&p, s); return (float*)p; }
static __nv_bfloat16* sym_b(const void* s) { void* p = nullptr; cudaGetSymbolAddress(&p, s); return (__nv_bfloat16*)p; }

#define ZCMMA_SMEM 81920

extern "C" void kernel_launch(void* const* d_in, const int* in_sizes, int n_in,
                              void* d_out, int out_size)
{
    const float* x  = (const float*)d_in[0];
    const float* cb = (const float*)d_in[1];
    const float* Wi = (const float*)d_in[2];
    const float* bi = (const float*)d_in[3];
    const float* Wc = (const float*)d_in[4];
    const float* bc = (const float*)d_in[5];
    float* out = (float*)d_out;

    float* zi_pre = sym_f(g_zi_pre);
    float* zi     = sym_f(g_zi);
    float* zc     = sym_f(g_zc);
    float* zcn    = sym_f(g_zcn);
    __nv_bfloat16* zih = sym_b(g_zih);
    __nv_bfloat16* zch = sym_b(g_zch);
    __nv_bfloat16* cbh = sym_b(g_cbh);
    __nv_bfloat16* cbl = sym_b(g_cbl);
    __nv_bfloat16* wth = sym_b(g_wth);
    __nv_bfloat16* wtl = sym_b(g_wtl);
    __nv_bfloat16* scores = sym_b(g_scores);
    __nv_bfloat16* bmax   = sym_b(g_bmax);

    cudaFuncSetAttribute(zc_mma, cudaFuncAttributeMaxDynamicSharedMemorySize, ZCMMA_SMEM);

    init_k<<<64, 256>>>();
    // bf16 hi/lo splits of codebook + W_code^T
    splitcb_k<<<1024, 256>>>((const float4*)cb, (uint2*)cbh, (uint2*)cbl,
                             VOC * DDIM / 4);
    wsplit_k<<<(LDIM * DDIM + 255) / 256, 256>>>(Wc, wth, wtl);
    // zi_pre = x @ W_in + b_in ; zi = l2n(zi_pre) (+ bf16 copy)  [exact fp32]
    gemm_k<<<dim3(NTOK / 64, LDIM / 64), 256>>>(x, Wi, bi, zi_pre, NTOK);
    norm_k<<<NTOK / 8, 256>>>(zi_pre, zi, zih, nullptr, NTOK);
    // zc_pre = cb @ W_code + b_code via 3-product bf16-split tensor MMA
    zc_mma<<<dim3((VOC + 127) / 128, LDIM / 128), 256, ZCMMA_SMEM>>>(
        cbh, cbl, wth, wtl, bc, zc);
    norm_k<<<(VOC + 7) / 8, 256>>>(zc, zc, zch, zcn, VOC);
    // K1: bf16 MMA scores (cp.async + ldmatrix) -> gmem + blockmax
    score_mma<<<dim3(NTOK / 128, VOCP / 128), 256>>>(zih, zch, scores, bmax);
    // K2: block-select + prune + exact top-4 + histogram
    select_k<<<NTOK / 4, 128>>>(bmax, scores, zi, zc);
    // quantize + STE output + mse1
    quant_k<<<NTOK / 8, 256>>>(x, cb, out);
    // mse2 without a GEMM: q@Wc+b == mean of selected zc_pre rows
    mse2_k<<<NTOK / 8, 256>>>(zc, zcn, zi_pre);
    ent_k<<<64, 256>>>();
    fin_k<<<1, 1>>>(out + (size_t)NTOK * DDIM);
}